// round 6
// baseline (speedup 1.0000x reference)
#include <cuda_runtime.h>
#include <cstdint>
#include <cstddef>

#define BATCH 256
#define SEQ   128
#define DM    1024
#define HS    1024

// Scratch (device globals: allocation-guard-safe)
__device__ float g_T[(size_t)BATCH * SEQ * HS];   // x_q * M
__device__ float g_V[(size_t)BATCH * SEQ * HS];   // x_v * W_v
__device__ float g_M[(size_t)DM * DM];            // W_q * W_k^T

// ===========================================================================
// Helpers
// ===========================================================================
__device__ __forceinline__ uint32_t smem_u32(const void* p) {
    uint32_t a;
    asm("{ .reg .u64 t; cvta.to.shared.u64 t, %1; cvt.u32.u64 %0, t; }"
        : "=r"(a) : "l"(p));
    return a;
}

__device__ __forceinline__ uint32_t f2tf32(float x) {
    uint32_t y;
    asm("cvt.rna.tf32.f32 %0, %1;" : "=r"(y) : "f"(x));
    return y;
}

__device__ __forceinline__ void mma_tf32(float* d, const uint32_t* a, const uint32_t* b) {
    asm volatile(
        "mma.sync.aligned.m16n8k8.row.col.f32.tf32.tf32.f32 "
        "{%0,%1,%2,%3}, {%4,%5,%6,%7}, {%8,%9}, {%0,%1,%2,%3};"
        : "+f"(d[0]), "+f"(d[1]), "+f"(d[2]), "+f"(d[3])
        : "r"(a[0]), "r"(a[1]), "r"(a[2]), "r"(a[3]), "r"(b[0]), "r"(b[1]));
}

__device__ __forceinline__ void cp_async16(uint32_t dst_smem, const void* src) {
    asm volatile("cp.async.cg.shared.global [%0], [%1], 16;"
                 :: "r"(dst_smem), "l"(src));
}
__device__ __forceinline__ void cp_commit() {
    asm volatile("cp.async.commit_group;");
}
template <int N>
__device__ __forceinline__ void cp_wait() {
    asm volatile("cp.async.wait_group %0;" :: "n"(N));
}

// ===========================================================================
// Shared tile-GEMM pitches
// ===========================================================================
#define SP 20                       // K-major operand pitch (NT / attn)
#define A_PITCH 20
#define B_PITCH 136
#define A_STAGE (128 * A_PITCH)
#define B_STAGE (16 * B_PITCH)
#define STAGE_FLOATS (A_STAGE + B_STAGE)
#define NSTAGES 3
#define PROJ_SMEM_BYTES (NSTAGES * STAGE_FLOATS * 4)
#define NT_STAGE (2 * 128 * SP)     // floats per NT stage (A + B)

// ===========================================================================
// NT GEMM body: C[i,j] = sum_h A[i,h]*B[j,h]  (128x128 tile, K=1024)
// ===========================================================================
__device__ __forceinline__ void gemm_nt_body(const float* __restrict__ A,
                                             const float* __restrict__ B,
                                             float* __restrict__ C,
                                             float* sm, uint32_t smb,
                                             int m0, int n0, int ldc)
{
    const int tid  = threadIdx.x;
    const int wid  = tid >> 5;
    const int lane = tid & 31;
    const int g    = lane >> 2;
    const int tg   = lane & 3;
    const int wm   = wid >> 1;
    const int wn   = wid & 1;

    const int r0 = tid >> 2, qq = tid & 3;
    const int r1 = (tid + 256) >> 2;

    float acc[2][8][4];
    #pragma unroll
    for (int i = 0; i < 2; i++)
        #pragma unroll
        for (int j = 0; j < 8; j++)
            #pragma unroll
            for (int c = 0; c < 4; c++) acc[i][j][c] = 0.f;

    auto load_s = [&](int ks, int buf) {
        const int k0 = ks * 16;
        const uint32_t sa = smb + (uint32_t)(buf * NT_STAGE) * 4u;
        const uint32_t sb = sa + (uint32_t)(128 * SP) * 4u;
        cp_async16(sa + (uint32_t)(r0 * SP + qq * 4) * 4u, A + (size_t)(m0 + r0) * DM + k0 + qq * 4);
        cp_async16(sa + (uint32_t)(r1 * SP + qq * 4) * 4u, A + (size_t)(m0 + r1) * DM + k0 + qq * 4);
        cp_async16(sb + (uint32_t)(r0 * SP + qq * 4) * 4u, B + (size_t)(n0 + r0) * DM + k0 + qq * 4);
        cp_async16(sb + (uint32_t)(r1 * SP + qq * 4) * 4u, B + (size_t)(n0 + r1) * DM + k0 + qq * 4);
    };

    load_s(0, 0); cp_commit();
    for (int i = 0; i < 64; i++) {
        if (i + 1 < 64) { load_s(i + 1, (i + 1) & 1); cp_commit(); cp_wait<1>(); }
        else            { cp_wait<0>(); }
        __syncthreads();
        const float* As = sm + (i & 1) * NT_STAGE;
        const float* Bs = As + 128 * SP;

        #pragma unroll
        for (int kk = 0; kk < 16; kk += 8) {
            uint32_t afr[2][4];
            #pragma unroll
            for (int mt = 0; mt < 2; mt++) {
                const int m = wm * 32 + mt * 16;
                afr[mt][0] = f2tf32(As[(m + g)     * SP + kk + tg]);
                afr[mt][1] = f2tf32(As[(m + g + 8) * SP + kk + tg]);
                afr[mt][2] = f2tf32(As[(m + g)     * SP + kk + tg + 4]);
                afr[mt][3] = f2tf32(As[(m + g + 8) * SP + kk + tg + 4]);
            }
            uint32_t bfr[8][2];
            #pragma unroll
            for (int nt = 0; nt < 8; nt++) {
                const int n = wn * 64 + nt * 8;
                bfr[nt][0] = f2tf32(Bs[(n + g) * SP + kk + tg]);
                bfr[nt][1] = f2tf32(Bs[(n + g) * SP + kk + tg + 4]);
            }
            #pragma unroll
            for (int mt = 0; mt < 2; mt++)
                #pragma unroll
                for (int nt = 0; nt < 8; nt++)
                    mma_tf32(acc[mt][nt], afr[mt], bfr[nt]);
        }
        __syncthreads();
    }

    #pragma unroll
    for (int mt = 0; mt < 2; mt++) {
        const int mrow = m0 + wm * 32 + mt * 16;
        #pragma unroll
        for (int nt = 0; nt < 8; nt++) {
            const int ncol = n0 + wn * 64 + nt * 8 + 2 * tg;
            *reinterpret_cast<float2*>(C + (size_t)(mrow + g) * ldc + ncol) =
                make_float2(acc[mt][nt][0], acc[mt][nt][1]);
            *reinterpret_cast<float2*>(C + (size_t)(mrow + g + 8) * ldc + ncol) =
                make_float2(acc[mt][nt][2], acc[mt][nt][3]);
        }
    }
}

// ===========================================================================
// NN GEMM body: C = A[M,K]*B[K,N] (128x128 tile, K=1024), 3-stage pipeline
// ===========================================================================
__device__ __forceinline__ void gemm_nn_body(const float* __restrict__ A,
                                             const float* __restrict__ Bw,
                                             float* __restrict__ C,
                                             float* sm, uint32_t smb,
                                             int m0, int n0)
{
    const int tid  = threadIdx.x;
    const int wid  = tid >> 5;
    const int lane = tid & 31;
    const int g    = lane >> 2;
    const int tg   = lane & 3;
    const int wm   = wid >> 1;
    const int wn   = wid & 1;

    const int arow0 = tid >> 2,         aq0 = tid & 3;
    const int arow1 = (tid + 256) >> 2;
    const int brow0 = tid >> 5,         bc0 = tid & 31;
    const int brow1 = (tid + 256) >> 5;

    float acc[2][8][4];
    #pragma unroll
    for (int i = 0; i < 2; i++)
        #pragma unroll
        for (int j = 0; j < 8; j++)
            #pragma unroll
            for (int c = 0; c < 4; c++) acc[i][j][c] = 0.f;

    auto load_stage = [&](int ks, int buf) {
        const int k0 = ks * 16;
        const uint32_t sa = smb + (uint32_t)(buf * STAGE_FLOATS) * 4u;
        const uint32_t sb = sa + (uint32_t)A_STAGE * 4u;
        cp_async16(sa + (uint32_t)(arow0 * A_PITCH + aq0 * 4) * 4u,
                   A + (size_t)(m0 + arow0) * DM + k0 + aq0 * 4);
        cp_async16(sa + (uint32_t)(arow1 * A_PITCH + aq0 * 4) * 4u,
                   A + (size_t)(m0 + arow1) * DM + k0 + aq0 * 4);
        cp_async16(sb + (uint32_t)(brow0 * B_PITCH + bc0 * 4) * 4u,
                   Bw + (size_t)(k0 + brow0) * HS + n0 + bc0 * 4);
        cp_async16(sb + (uint32_t)(brow1 * B_PITCH + bc0 * 4) * 4u,
                   Bw + (size_t)(k0 + brow1) * HS + n0 + bc0 * 4);
    };

    load_stage(0, 0); cp_commit();
    load_stage(1, 1); cp_commit();

    const int NK = DM / 16;
    for (int i = 0; i < NK; i++) {
        cp_wait<1>();
        __syncthreads();
        if (i + 2 < NK) load_stage(i + 2, (i + 2) % NSTAGES);
        cp_commit();

        const float* As = sm + (i % NSTAGES) * STAGE_FLOATS;
        const float* Bs = As + A_STAGE;

        #pragma unroll
        for (int kk = 0; kk < 16; kk += 8) {
            uint32_t afr[2][4];
            #pragma unroll
            for (int mt = 0; mt < 2; mt++) {
                const int m = wm * 32 + mt * 16;
                afr[mt][0] = f2tf32(As[(m + g)     * A_PITCH + kk + tg]);
                afr[mt][1] = f2tf32(As[(m + g + 8) * A_PITCH + kk + tg]);
                afr[mt][2] = f2tf32(As[(m + g)     * A_PITCH + kk + tg + 4]);
                afr[mt][3] = f2tf32(As[(m + g + 8) * A_PITCH + kk + tg + 4]);
            }
            uint32_t bfr[8][2];
            #pragma unroll
            for (int nt = 0; nt < 8; nt++) {
                const int n = wn * 64 + nt * 8;
                bfr[nt][0] = f2tf32(Bs[(kk + tg)     * B_PITCH + n + g]);
                bfr[nt][1] = f2tf32(Bs[(kk + tg + 4) * B_PITCH + n + g]);
            }
            #pragma unroll
            for (int mt = 0; mt < 2; mt++)
                #pragma unroll
                for (int nt = 0; nt < 8; nt++)
                    mma_tf32(acc[mt][nt], afr[mt], bfr[nt]);
        }
        __syncthreads();
    }

    #pragma unroll
    for (int mt = 0; mt < 2; mt++) {
        const int mrow = m0 + wm * 32 + mt * 16;
        #pragma unroll
        for (int nt = 0; nt < 8; nt++) {
            const int ncol = n0 + wn * 64 + nt * 8 + 2 * tg;
            *reinterpret_cast<float2*>(C + (size_t)(mrow + g) * HS + ncol) =
                make_float2(acc[mt][nt][0], acc[mt][nt][1]);
            *reinterpret_cast<float2*>(C + (size_t)(mrow + g + 8) * HS + ncol) =
                make_float2(acc[mt][nt][2], acc[mt][nt][3]);
        }
    }
}

// ===========================================================================
// Launch 1 (fused): z=0 -> v = value*W_v (256 CTAs); z=1 -> M = W_q*W_k^T
// (64 CTAs, remainder exit immediately).
// ===========================================================================
__global__ __launch_bounds__(256) void fused1(const float* __restrict__ v_in,
                                              const float* __restrict__ w_q,
                                              const float* __restrict__ w_k,
                                              const float* __restrict__ w_v,
                                              float* __restrict__ v_out,
                                              float* __restrict__ m_out)
{
    extern __shared__ float sm[];
    const uint32_t smb = smem_u32(sm);
    if (blockIdx.z == 0) {
        gemm_nn_body(v_in, w_v, v_out, sm, smb, blockIdx.y * 128, blockIdx.x * 128);
    } else {
        if (blockIdx.y >= 8) return;
        gemm_nt_body(w_q, w_k, m_out, sm, smb, blockIdx.y * 128, blockIdx.x * 128, DM);
    }
}

// Launch 2: T = query * M
__global__ __launch_bounds__(256) void proj_T(const float* __restrict__ q_in,
                                              const float* __restrict__ m_mat,
                                              float* __restrict__ t_out)
{
    extern __shared__ float sm[];
    const uint32_t smb = smem_u32(sm);
    gemm_nn_body(q_in, m_mat, t_out, sm, smb, blockIdx.y * 128, blockIdx.x * 128);
}

// ===========================================================================
// Attention (mma.sync tf32): one CTA per batch, 256 threads.
// S = T * x_k^T, causal softmax, O = P*v. V tile 0 prefetched before softmax.
// ===========================================================================
#define S_STAGE (2 * 128 * SP)
#define P_OFF   (2 * S_STAGE)
#define P_PITCH 132
#define VP 136
#define V_STAGE (16 * VP)
#define ATTN_SMEM ((P_OFF + 128 * P_PITCH) * 4)

__global__ __launch_bounds__(256) void attn_tc(const float* __restrict__ Kraw,
                                               float* __restrict__ O)
{
    extern __shared__ float sm[];
    const uint32_t smb = smem_u32(sm);

    const int tid  = threadIdx.x;
    const int wid  = tid >> 5;
    const int lane = tid & 31;
    const int g    = lane >> 2;
    const int tg   = lane & 3;
    const int wm   = wid >> 1;
    const int wn   = wid & 1;
    const int b    = blockIdx.x;

    const float* Qb = g_T + (size_t)b * SEQ * HS;
    const float* Kb = Kraw + (size_t)b * SEQ * DM;
    const float* Vb = g_V + (size_t)b * SEQ * HS;
    float* P = sm + P_OFF;

    float acc[2][8][4];
    #pragma unroll
    for (int i = 0; i < 2; i++)
        #pragma unroll
        for (int j = 0; j < 8; j++)
            #pragma unroll
            for (int c = 0; c < 4; c++) acc[i][j][c] = 0.f;

    // ---------------- Phase 1: S = T K^T ----------------
    const int r0 = tid >> 2, qq = tid & 3;
    const int r1 = (tid + 256) >> 2;

    auto load_s = [&](int ks, int buf) {
        const int k0 = ks * 16;
        const uint32_t sq = smb + (uint32_t)(buf * S_STAGE) * 4u;
        const uint32_t sk = sq + (uint32_t)(128 * SP) * 4u;
        cp_async16(sq + (uint32_t)(r0 * SP + qq * 4) * 4u, Qb + (size_t)r0 * HS + k0 + qq * 4);
        cp_async16(sq + (uint32_t)(r1 * SP + qq * 4) * 4u, Qb + (size_t)r1 * HS + k0 + qq * 4);
        cp_async16(sk + (uint32_t)(r0 * SP + qq * 4) * 4u, Kb + (size_t)r0 * DM + k0 + qq * 4);
        cp_async16(sk + (uint32_t)(r1 * SP + qq * 4) * 4u, Kb + (size_t)r1 * DM + k0 + qq * 4);
    };

    const int vr0 = tid >> 5, vc = tid & 31;
    const int vr1 = (tid + 256) >> 5;
    auto load_v = [&](int s) {
        const int nt = s >> 3, ki = s & 7;
        const uint32_t sv = smb + (uint32_t)((s & 1) * V_STAGE) * 4u;
        cp_async16(sv + (uint32_t)(vr0 * VP + vc * 4) * 4u,
                   Vb + (size_t)(ki * 16 + vr0) * HS + nt * 128 + vc * 4);
        cp_async16(sv + (uint32_t)(vr1 * VP + vc * 4) * 4u,
                   Vb + (size_t)(ki * 16 + vr1) * HS + nt * 128 + vc * 4);
    };

    load_s(0, 0); cp_commit();
    for (int i = 0; i < 64; i++) {
        if (i + 1 < 64) { load_s(i + 1, (i + 1) & 1); cp_commit(); cp_wait<1>(); }
        else            { cp_wait<0>(); }
        __syncthreads();
        const float* Qs = sm + (i & 1) * S_STAGE;
        const float* Ks = Qs + 128 * SP;

        #pragma unroll
        for (int kk = 0; kk < 16; kk += 8) {
            uint32_t afr[2][4];
            #pragma unroll
            for (int mt = 0; mt < 2; mt++) {
                const int m = wm * 32 + mt * 16;
                afr[mt][0] = f2tf32(Qs[(m + g)     * SP + kk + tg]);
                afr[mt][1] = f2tf32(Qs[(m + g + 8) * SP + kk + tg]);
                afr[mt][2] = f2tf32(Qs[(m + g)     * SP + kk + tg + 4]);
                afr[mt][3] = f2tf32(Qs[(m + g + 8) * SP + kk + tg + 4]);
            }
            uint32_t bfr[8][2];
            #pragma unroll
            for (int nt = 0; nt < 8; nt++) {
                const int n = wn * 64 + nt * 8;
                bfr[nt][0] = f2tf32(Ks[(n + g) * SP + kk + tg]);
                bfr[nt][1] = f2tf32(Ks[(n + g) * SP + kk + tg + 4]);
            }
            #pragma unroll
            for (int mt = 0; mt < 2; mt++)
                #pragma unroll
                for (int nt = 0; nt < 8; nt++)
                    mma_tf32(acc[mt][nt], afr[mt], bfr[nt]);
        }
        __syncthreads();
    }

    // prefetch V tile 0 (stage-0 smem region is dead now) — overlaps softmax
    load_v(0); cp_commit();

    const float scale = 0.03125f;
    #pragma unroll
    for (int mt = 0; mt < 2; mt++) {
        const int mrow = wm * 32 + mt * 16;
        #pragma unroll
        for (int nt = 0; nt < 8; nt++) {
            const int ncol = wn * 64 + nt * 8 + 2 * tg;
            P[(mrow + g) * P_PITCH + ncol]     = acc[mt][nt][0] * scale;
            P[(mrow + g) * P_PITCH + ncol + 1] = acc[mt][nt][1] * scale;
            P[(mrow + g + 8) * P_PITCH + ncol]     = acc[mt][nt][2] * scale;
            P[(mrow + g + 8) * P_PITCH + ncol + 1] = acc[mt][nt][3] * scale;
        }
    }
    __syncthreads();

    // ---------------- Phase 2: causal softmax (warp per row) ----------------
    #pragma unroll 1
    for (int i = 0; i < 16; i++) {
        const int r = wid * 16 + i;
        float x[4];
        #pragma unroll
        for (int j = 0; j < 4; j++) {
            const int col = lane + 32 * j;
            x[j] = (col <= r) ? P[r * P_PITCH + col] : -1e30f;
        }
        float m = fmaxf(fmaxf(x[0], x[1]), fmaxf(x[2], x[3]));
        #pragma unroll
        for (int o = 16; o > 0; o >>= 1) m = fmaxf(m, __shfl_xor_sync(0xffffffffu, m, o));
        float e[4], s = 0.f;
        #pragma unroll
        for (int j = 0; j < 4; j++) {
            const int col = lane + 32 * j;
            e[j] = (col <= r) ? __expf(x[j] - m) : 0.f;
            s += e[j];
        }
        #pragma unroll
        for (int o = 16; o > 0; o >>= 1) s += __shfl_xor_sync(0xffffffffu, s, o);
        const float inv = 1.f / s;
        #pragma unroll
        for (int j = 0; j < 4; j++)
            P[r * P_PITCH + lane + 32 * j] = e[j] * inv;
    }
    __syncthreads();

    // ---------------- Phase 3: O = P V ----------------
    for (int nt = 0; nt < 8; nt++) {
        #pragma unroll
        for (int i = 0; i < 2; i++)
            #pragma unroll
            for (int j = 0; j < 8; j++)
                #pragma unroll
                for (int c = 0; c < 4; c++) acc[i][j][c] = 0.f;

        for (int ki = 0; ki < 8; ki++) {
            const int s = nt * 8 + ki;
            if (s + 1 < 64) { load_v(s + 1); cp_commit(); cp_wait<1>(); }
            else            { cp_wait<0>(); }
            __syncthreads();
            const float* Vs = sm + (s & 1) * V_STAGE;

            #pragma unroll
            for (int kk = 0; kk < 16; kk += 8) {
                const int kc = ki * 16 + kk;
                uint32_t afr[2][4];
                #pragma unroll
                for (int mt = 0; mt < 2; mt++) {
                    const int m = wm * 32 + mt * 16;
                    afr[mt][0] = f2tf32(P[(m + g)     * P_PITCH + kc + tg]);
                    afr[mt][1] = f2tf32(P[(m + g + 8) * P_PITCH + kc + tg]);
                    afr[mt][2] = f2tf32(P[(m + g)     * P_PITCH + kc + tg + 4]);
                    afr[mt][3] = f2tf32(P[(m + g + 8) * P_PITCH + kc + tg + 4]);
                }
                uint32_t bfr[8][2];
                #pragma unroll
                for (int nt2 = 0; nt2 < 8; nt2++) {
                    const int n = wn * 64 + nt2 * 8;
                    bfr[nt2][0] = f2tf32(Vs[(kk + tg)     * VP + n + g]);
                    bfr[nt2][1] = f2tf32(Vs[(kk + tg + 4) * VP + n + g]);
                }
                #pragma unroll
                for (int mt = 0; mt < 2; mt++)
                    #pragma unroll
                    for (int nt2 = 0; nt2 < 8; nt2++)
                        mma_tf32(acc[mt][nt2], afr[mt], bfr[nt2]);
            }
            __syncthreads();
        }

        #pragma unroll
        for (int mt = 0; mt < 2; mt++) {
            const int mrow = wm * 32 + mt * 16;
            #pragma unroll
            for (int nt2 = 0; nt2 < 8; nt2++) {
                const int ncol = nt * 128 + wn * 64 + nt2 * 8 + 2 * tg;
                *reinterpret_cast<float2*>(
                    O + ((size_t)b * SEQ + mrow + g) * HS + ncol) =
                    make_float2(acc[mt][nt2][0], acc[mt][nt2][1]);
                *reinterpret_cast<float2*>(
                    O + ((size_t)b * SEQ + mrow + g + 8) * HS + ncol) =
                    make_float2(acc[mt][nt2][2], acc[mt][nt2][3]);
            }
        }
    }
}

// ===========================================================================
extern "C" void kernel_launch(void* const* d_in, const int* in_sizes, int n_in,
                              void* d_out, int out_size)
{
    const float* query = (const float*)d_in[0];
    const float* key   = (const float*)d_in[1];
    const float* value = (const float*)d_in[2];
    const float* w_q   = (const float*)d_in[3];
    const float* w_k   = (const float*)d_in[4];
    const float* w_v   = (const float*)d_in[5];
    float* out = (float*)d_out;

    float *Tp, *Vp, *Mp;
    cudaGetSymbolAddress((void**)&Tp, g_T);
    cudaGetSymbolAddress((void**)&Vp, g_V);
    cudaGetSymbolAddress((void**)&Mp, g_M);

    // Launch 1: v = value*W_v fused with M = W_q*W_k^T
    cudaFuncSetAttribute(fused1, cudaFuncAttributeMaxDynamicSharedMemorySize, PROJ_SMEM_BYTES);
    fused1<<<dim3(8, 256, 2), 256, PROJ_SMEM_BYTES>>>(value, w_q, w_k, w_v, Vp, Mp);

    // Launch 2: T = query * M
    cudaFuncSetAttribute(proj_T, cudaFuncAttributeMaxDynamicSharedMemorySize, PROJ_SMEM_BYTES);
    proj_T<<<dim3(8, 256), 256, PROJ_SMEM_BYTES>>>(query, Mp, Tp);

    // Launch 3: attention with raw key as second operand
    cudaFuncSetAttribute(attn_tc, cudaFuncAttributeMaxDynamicSharedMemorySize, ATTN_SMEM);
    attn_tc<<<BATCH, 256, ATTN_SMEM>>>(key, out);
}

// round 7
// speedup vs baseline: 1.4791x; 1.4791x over previous
#include <cuda_runtime.h>
#include <cuda_fp16.h>
#include <cstdint>
#include <cstddef>

#define BATCH 256
#define SEQ   128
#define DM    1024
#define HS    1024

// fp16 scratch (device globals: allocation-guard-safe)
__device__ __half g_q16[(size_t)BATCH * SEQ * DM];    // query fp16
__device__ __half g_k16[(size_t)BATCH * SEQ * DM];    // key fp16
__device__ __half g_x16[(size_t)BATCH * SEQ * DM];    // value input fp16
__device__ __half g_wq16[(size_t)DM * HS];
__device__ __half g_wk16[(size_t)DM * HS];
__device__ __half g_wvT16[(size_t)HS * DM];           // [n][h] = W_v[h][n]
__device__ __half g_MT16[(size_t)DM * DM];            // [n][k] = (W_q W_k^T)[k][n]
__device__ __half g_T16[(size_t)BATCH * SEQ * HS];    // [m][n] = q * M
__device__ __half g_vT16[(size_t)BATCH * HS * SEQ];   // [b][n][s] = v^T

// ===========================================================================
// Helpers
// ===========================================================================
__device__ __forceinline__ uint32_t smem_u32(const void* p) {
    uint32_t a;
    asm("{ .reg .u64 t; cvta.to.shared.u64 t, %1; cvt.u32.u64 %0, t; }"
        : "=r"(a) : "l"(p));
    return a;
}

__device__ __forceinline__ void mma_f16(float* d, const uint32_t* a, const uint32_t* b) {
    asm volatile(
        "mma.sync.aligned.m16n8k16.row.col.f32.f16.f16.f32 "
        "{%0,%1,%2,%3}, {%4,%5,%6,%7}, {%8,%9}, {%0,%1,%2,%3};"
        : "+f"(d[0]), "+f"(d[1]), "+f"(d[2]), "+f"(d[3])
        : "r"(a[0]), "r"(a[1]), "r"(a[2]), "r"(a[3]), "r"(b[0]), "r"(b[1]));
}

__device__ __forceinline__ void cp_async16(uint32_t dst_smem, const void* src) {
    asm volatile("cp.async.cg.shared.global [%0], [%1], 16;"
                 :: "r"(dst_smem), "l"(src));
}
__device__ __forceinline__ void cp_commit() {
    asm volatile("cp.async.commit_group;");
}
template <int N>
__device__ __forceinline__ void cp_wait() {
    asm volatile("cp.async.wait_group %0;" :: "n"(N));
}

// ===========================================================================
// Pre-pass: fp32 -> fp16 conversions
// ===========================================================================
__global__ __launch_bounds__(256) void cvt_big(const float* __restrict__ q,
                                               const float* __restrict__ k,
                                               const float* __restrict__ v)
{
    const float* src = (blockIdx.z == 0) ? q : (blockIdx.z == 1) ? k : v;
    __half* dst = (blockIdx.z == 0) ? g_q16 : (blockIdx.z == 1) ? g_k16 : g_x16;
    const size_t i = (size_t)blockIdx.x * 256 + threadIdx.x;
    const size_t stride = 2097152;   // 8388608 float4s / 4
    #pragma unroll
    for (int j = 0; j < 4; j++) {
        size_t idx = i + (size_t)j * stride;
        float4 f = reinterpret_cast<const float4*>(src)[idx];
        __half2 h0 = __float22half2_rn(make_float2(f.x, f.y));
        __half2 h1 = __float22half2_rn(make_float2(f.z, f.w));
        reinterpret_cast<__half2*>(dst)[idx * 2 + 0] = h0;
        reinterpret_cast<__half2*>(dst)[idx * 2 + 1] = h1;
    }
}

__global__ __launch_bounds__(256) void cvt_w(const float* __restrict__ wq,
                                             const float* __restrict__ wk)
{
    const float* src = blockIdx.z ? wk : wq;
    __half* dst = blockIdx.z ? g_wk16 : g_wq16;
    const size_t i = (size_t)blockIdx.x * 256 + threadIdx.x;
    const size_t stride = 65536;     // 262144 float4s / 4
    #pragma unroll
    for (int j = 0; j < 4; j++) {
        size_t idx = i + (size_t)j * stride;
        float4 f = reinterpret_cast<const float4*>(src)[idx];
        __half2 h0 = __float22half2_rn(make_float2(f.x, f.y));
        __half2 h1 = __float22half2_rn(make_float2(f.z, f.w));
        reinterpret_cast<__half2*>(dst)[idx * 2 + 0] = h0;
        reinterpret_cast<__half2*>(dst)[idx * 2 + 1] = h1;
    }
}

// wvT[n][h] = wv[h][n]
__global__ __launch_bounds__(256) void trans_wv(const float* __restrict__ wv)
{
    __shared__ float t[32][33];
    const int tx = threadIdx.x & 31, ty = threadIdx.x >> 5;   // ty 0..7
    const int x0 = blockIdx.x * 32, y0 = blockIdx.y * 32;
    #pragma unroll
    for (int j = 0; j < 4; j++)
        t[ty + 8 * j][tx] = wv[(size_t)(y0 + ty + 8 * j) * HS + x0 + tx];
    __syncthreads();
    #pragma unroll
    for (int j = 0; j < 4; j++)
        g_wvT16[(size_t)(x0 + ty + 8 * j) * DM + y0 + tx] =
            __float2half_rn(t[tx][ty + 8 * j]);
}

// ===========================================================================
// Uniform fp16 NT GEMM body: C[m][n] = sum_k A[m][k]*B[n][k]  (fp32 accum)
// CTA tile 128x128, BK=16, 3-stage cp.async pipeline, 8 warps (32m x 64n).
// SMEM pitches 24 halfwords -> conflict-free 32-bit fragment LDS.
// ===========================================================================
#define PA 24
#define PB 24
#define AST (128 * PA)            // halfwords per A stage
#define BST (128 * PB)
#define STG_H (AST + BST)         // 6144 halfwords = 12288 B
#define NST 3
#define GEMM_SMEM (NST * STG_H * 2)   // 36864 B

__device__ __forceinline__ void gemm_nt_f16(const __half* __restrict__ A,
                                            const __half* __restrict__ B,
                                            __half* __restrict__ C,
                                            __half* sm, uint32_t smb,
                                            int m0, int n0, int ldc)
{
    const int tid  = threadIdx.x;
    const int wid  = tid >> 5;
    const int lane = tid & 31;
    const int g    = lane >> 2;
    const int tg   = lane & 3;
    const int wm   = wid >> 1;
    const int wn   = wid & 1;
    const int row  = tid >> 1, hf = tid & 1;

    float acc[2][8][4];
    #pragma unroll
    for (int i = 0; i < 2; i++)
        #pragma unroll
        for (int j = 0; j < 8; j++)
            #pragma unroll
            for (int c = 0; c < 4; c++) acc[i][j][c] = 0.f;

    auto load_stage = [&](int ks, int buf) {
        const int k0 = ks * 16;
        const uint32_t sa = smb + (uint32_t)(buf * STG_H) * 2u;
        const uint32_t sb = sa + (uint32_t)AST * 2u;
        cp_async16(sa + row * 48 + hf * 16, A + (size_t)(m0 + row) * DM + k0 + hf * 8);
        cp_async16(sb + row * 48 + hf * 16, B + (size_t)(n0 + row) * DM + k0 + hf * 8);
    };

    load_stage(0, 0); cp_commit();
    load_stage(1, 1); cp_commit();

    for (int i = 0; i < 64; i++) {
        cp_wait<1>();
        __syncthreads();
        if (i + 2 < 64) load_stage(i + 2, (i + 2) % NST);
        cp_commit();

        const __half* As = sm + (i % NST) * STG_H;
        const __half* Bs = As + AST;

        uint32_t a[2][4], bf[8][2];
        #pragma unroll
        for (int mt = 0; mt < 2; mt++) {
            const int m = wm * 32 + mt * 16;
            a[mt][0] = *reinterpret_cast<const uint32_t*>(As + (m + g)     * PA + 2 * tg);
            a[mt][1] = *reinterpret_cast<const uint32_t*>(As + (m + g + 8) * PA + 2 * tg);
            a[mt][2] = *reinterpret_cast<const uint32_t*>(As + (m + g)     * PA + 2 * tg + 8);
            a[mt][3] = *reinterpret_cast<const uint32_t*>(As + (m + g + 8) * PA + 2 * tg + 8);
        }
        #pragma unroll
        for (int nt = 0; nt < 8; nt++) {
            const int n = wn * 64 + nt * 8;
            bf[nt][0] = *reinterpret_cast<const uint32_t*>(Bs + (n + g) * PB + 2 * tg);
            bf[nt][1] = *reinterpret_cast<const uint32_t*>(Bs + (n + g) * PB + 2 * tg + 8);
        }
        #pragma unroll
        for (int mt = 0; mt < 2; mt++)
            #pragma unroll
            for (int nt = 0; nt < 8; nt++)
                mma_f16(acc[mt][nt], a[mt], bf[nt]);
        __syncthreads();
    }

    #pragma unroll
    for (int mt = 0; mt < 2; mt++) {
        const int mrow = m0 + wm * 32 + mt * 16;
        #pragma unroll
        for (int nt = 0; nt < 8; nt++) {
            const int ncol = n0 + wn * 64 + nt * 8 + 2 * tg;
            *reinterpret_cast<__half2*>(C + (size_t)(mrow + g) * ldc + ncol) =
                __float22half2_rn(make_float2(acc[mt][nt][0], acc[mt][nt][1]));
            *reinterpret_cast<__half2*>(C + (size_t)(mrow + g + 8) * ldc + ncol) =
                __float22half2_rn(make_float2(acc[mt][nt][2], acc[mt][nt][3]));
        }
    }
}

// MT[i][j] = sum_h wk[i][h]*wq[j][h]   (= M[j][i]); grid (8,8)
__global__ __launch_bounds__(256, 2) void gemm_M()
{
    extern __shared__ __half sm[];
    gemm_nt_f16(g_wk16, g_wq16, g_MT16, sm, smem_u32(sm),
                blockIdx.y * 128, blockIdx.x * 128, DM);
}

// z=0: T = q*M (A=q16, B=MT);  z=1: vT_b[n][s] = sum_h wvT[n][h]*x_b[s][h]
__global__ __launch_bounds__(256, 2) void proj_f16()
{
    extern __shared__ __half sm[];
    const uint32_t smb = smem_u32(sm);
    if (blockIdx.z == 0) {
        gemm_nt_f16(g_q16, g_MT16, g_T16, sm, smb,
                    blockIdx.y * 128, blockIdx.x * 128, HS);
    } else {
        gemm_nt_f16(g_wvT16, g_x16 + (size_t)blockIdx.y * SEQ * DM,
                    g_vT16 + (size_t)blockIdx.y * HS * SEQ, sm, smb,
                    blockIdx.x * 128, 0, SEQ);
    }
}

// ===========================================================================
// Attention: one CTA per batch. S = T*key^T -> fp16 P -> softmax -> O = P*vT.
// SMEM (halfwords): [0, 2*STG_H) phase-1 stages (V stages alias the front),
//                   [12288, +128*136) P.
// ===========================================================================
#define PP 136
#define P_HW 12288
#define ATTN_SMEM ((P_HW + 128 * PP) * 2)   // 59392 B

__global__ __launch_bounds__(256, 2) void attn_f16(float* __restrict__ O)
{
    extern __shared__ __half sm[];
    const uint32_t smb = smem_u32(sm);

    const int tid  = threadIdx.x;
    const int wid  = tid >> 5;
    const int lane = tid & 31;
    const int g    = lane >> 2;
    const int tg   = lane & 3;
    const int wm   = wid >> 1;
    const int wn   = wid & 1;
    const int row  = tid >> 1, hf = tid & 1;
    const int b    = blockIdx.x;

    const __half* Tb = g_T16 + (size_t)b * SEQ * HS;
    const __half* Kb = g_k16 + (size_t)b * SEQ * DM;
    const __half* Vb = g_vT16 + (size_t)b * HS * SEQ;
    __half* P = sm + P_HW;

    float acc[2][8][4];
    #pragma unroll
    for (int i = 0; i < 2; i++)
        #pragma unroll
        for (int j = 0; j < 8; j++)
            #pragma unroll
            for (int c = 0; c < 4; c++) acc[i][j][c] = 0.f;

    // ---------------- Phase 1: S = T K^T ----------------
    auto load_s = [&](int ks, int buf) {
        const int k0 = ks * 16;
        const uint32_t sa = smb + (uint32_t)(buf * STG_H) * 2u;
        const uint32_t sb = sa + (uint32_t)AST * 2u;
        cp_async16(sa + row * 48 + hf * 16, Tb + (size_t)row * HS + k0 + hf * 8);
        cp_async16(sb + row * 48 + hf * 16, Kb + (size_t)row * DM + k0 + hf * 8);
    };
    // phase-3 V stage loader (aliases phase-1 stage region; stage = BST halfwords)
    auto load_v = [&](int s) {
        const int ntile = s >> 3, ki = s & 7;
        const uint32_t sv = smb + (uint32_t)((s & 1) * BST) * 2u;
        cp_async16(sv + row * 48 + hf * 16,
                   Vb + (size_t)(ntile * 128 + row) * SEQ + ki * 16 + hf * 8);
    };

    load_s(0, 0); cp_commit();
    for (int i = 0; i < 64; i++) {
        if (i + 1 < 64) { load_s(i + 1, (i + 1) & 1); cp_commit(); cp_wait<1>(); }
        else            { cp_wait<0>(); }
        __syncthreads();
        const __half* As = sm + (i & 1) * STG_H;
        const __half* Bs = As + AST;

        uint32_t a[2][4], bf[8][2];
        #pragma unroll
        for (int mt = 0; mt < 2; mt++) {
            const int m = wm * 32 + mt * 16;
            a[mt][0] = *reinterpret_cast<const uint32_t*>(As + (m + g)     * PA + 2 * tg);
            a[mt][1] = *reinterpret_cast<const uint32_t*>(As + (m + g + 8) * PA + 2 * tg);
            a[mt][2] = *reinterpret_cast<const uint32_t*>(As + (m + g)     * PA + 2 * tg + 8);
            a[mt][3] = *reinterpret_cast<const uint32_t*>(As + (m + g + 8) * PA + 2 * tg + 8);
        }
        #pragma unroll
        for (int nt = 0; nt < 8; nt++) {
            const int n = wn * 64 + nt * 8;
            bf[nt][0] = *reinterpret_cast<const uint32_t*>(Bs + (n + g) * PB + 2 * tg);
            bf[nt][1] = *reinterpret_cast<const uint32_t*>(Bs + (n + g) * PB + 2 * tg + 8);
        }
        #pragma unroll
        for (int mt = 0; mt < 2; mt++)
            #pragma unroll
            for (int nt = 0; nt < 8; nt++)
                mma_f16(acc[mt][nt], a[mt], bf[nt]);
        __syncthreads();
    }

    // prefetch V stage 0 (phase-1 stage region is dead) — overlaps softmax
    load_v(0); cp_commit();

    // scaled scores -> fp16 P
    const float scale = 0.03125f;
    #pragma unroll
    for (int mt = 0; mt < 2; mt++) {
        const int mrow = wm * 32 + mt * 16;
        #pragma unroll
        for (int nt = 0; nt < 8; nt++) {
            const int ncol = wn * 64 + nt * 8 + 2 * tg;
            *reinterpret_cast<__half2*>(P + (mrow + g) * PP + ncol) =
                __float22half2_rn(make_float2(acc[mt][nt][0] * scale, acc[mt][nt][1] * scale));
            *reinterpret_cast<__half2*>(P + (mrow + g + 8) * PP + ncol) =
                __float22half2_rn(make_float2(acc[mt][nt][2] * scale, acc[mt][nt][3] * scale));
        }
    }
    __syncthreads();

    // ---------------- Phase 2: causal softmax (warp per row) ----------------
    #pragma unroll 1
    for (int i = 0; i < 16; i++) {
        const int r = wid * 16 + i;
        float x[4];
        #pragma unroll
        for (int j = 0; j < 4; j++) {
            const int col = lane + 32 * j;
            x[j] = (col <= r) ? __half2float(P[r * PP + col]) : -1e30f;
        }
        float m = fmaxf(fmaxf(x[0], x[1]), fmaxf(x[2], x[3]));
        #pragma unroll
        for (int o = 16; o > 0; o >>= 1) m = fmaxf(m, __shfl_xor_sync(0xffffffffu, m, o));
        float e[4], s = 0.f;
        #pragma unroll
        for (int j = 0; j < 4; j++) {
            const int col = lane + 32 * j;
            e[j] = (col <= r) ? __expf(x[j] - m) : 0.f;
            s += e[j];
        }
        #pragma unroll
        for (int o = 16; o > 0; o >>= 1) s += __shfl_xor_sync(0xffffffffu, s, o);
        const float inv = 1.f / s;
        #pragma unroll
        for (int j = 0; j < 4; j++)
            P[r * PP + lane + 32 * j] = __float2half_rn(e[j] * inv);
    }
    __syncthreads();

    // ---------------- Phase 3: O = P * vT ----------------
    for (int nt = 0; nt < 8; nt++) {
        #pragma unroll
        for (int i = 0; i < 2; i++)
            #pragma unroll
            for (int j = 0; j < 8; j++)
                #pragma unroll
                for (int c = 0; c < 4; c++) acc[i][j][c] = 0.f;

        for (int ki = 0; ki < 8; ki++) {
            const int s = nt * 8 + ki;
            if (s + 1 < 64) { load_v(s + 1); cp_commit(); cp_wait<1>(); }
            else            { cp_wait<0>(); }
            __syncthreads();
            const __half* Vs = sm + (s & 1) * BST;
            const int kc = ki * 16;

            uint32_t a[2][4], bf[8][2];
            #pragma unroll
            for (int mt = 0; mt < 2; mt++) {
                const int m = wm * 32 + mt * 16;
                a[mt][0] = *reinterpret_cast<const uint32_t*>(P + (m + g)     * PP + kc + 2 * tg);
                a[mt][1] = *reinterpret_cast<const uint32_t*>(P + (m + g + 8) * PP + kc + 2 * tg);
                a[mt][2] = *reinterpret_cast<const uint32_t*>(P + (m + g)     * PP + kc + 2 * tg + 8);
                a[mt][3] = *reinterpret_cast<const uint32_t*>(P + (m + g + 8) * PP + kc + 2 * tg + 8);
            }
            #pragma unroll
            for (int nt2 = 0; nt2 < 8; nt2++) {
                const int n = wn * 64 + nt2 * 8;
                bf[nt2][0] = *reinterpret_cast<const uint32_t*>(Vs + (n + g) * PB + 2 * tg);
                bf[nt2][1] = *reinterpret_cast<const uint32_t*>(Vs + (n + g) * PB + 2 * tg + 8);
            }
            #pragma unroll
            for (int mt = 0; mt < 2; mt++)
                #pragma unroll
                for (int nt2 = 0; nt2 < 8; nt2++)
                    mma_f16(acc[mt][nt2], a[mt], bf[nt2]);
            __syncthreads();
        }

        #pragma unroll
        for (int mt = 0; mt < 2; mt++) {
            const int mrow = wm * 32 + mt * 16;
            #pragma unroll
            for (int nt2 = 0; nt2 < 8; nt2++) {
                const int ncol = nt * 128 + wn * 64 + nt2 * 8 + 2 * tg;
                *reinterpret_cast<float2*>(O + ((size_t)b * SEQ + mrow + g) * HS + ncol) =
                    make_float2(acc[mt][nt2][0], acc[mt][nt2][1]);
                *reinterpret_cast<float2*>(O + ((size_t)b * SEQ + mrow + g + 8) * HS + ncol) =
                    make_float2(acc[mt][nt2][2], acc[mt][nt2][3]);
            }
        }
    }
}

// ===========================================================================
extern "C" void kernel_launch(void* const* d_in, const int* in_sizes, int n_in,
                              void* d_out, int out_size)
{
    const float* query = (const float*)d_in[0];
    const float* key   = (const float*)d_in[1];
    const float* value = (const float*)d_in[2];
    const float* w_q   = (const float*)d_in[3];
    const float* w_k   = (const float*)d_in[4];
    const float* w_v   = (const float*)d_in[5];
    float* out = (float*)d_out;

    // Pre-pass conversions
    cvt_big<<<dim3(8192, 1, 3), 256>>>(query, key, value);
    cvt_w<<<dim3(256, 1, 2), 256>>>(w_q, w_k);
    trans_wv<<<dim3(32, 32), 256>>>(w_v);

    // MT = W_k * W_q^T
    cudaFuncSetAttribute(gemm_M, cudaFuncAttributeMaxDynamicSharedMemorySize, GEMM_SMEM);
    gemm_M<<<dim3(8, 8), 256, GEMM_SMEM>>>();

    // T = q*M  and  vT = W_v^T * x_v^T (per batch)
    cudaFuncSetAttribute(proj_f16, cudaFuncAttributeMaxDynamicSharedMemorySize, GEMM_SMEM);
    proj_f16<<<dim3(8, 256, 2), 256, GEMM_SMEM>>>();

    // attention
    cudaFuncSetAttribute(attn_f16, cudaFuncAttributeMaxDynamicSharedMemorySize, ATTN_SMEM);
    attn_f16<<<BATCH, 256, ATTN_SMEM>>>(out);
}

// round 8
// speedup vs baseline: 1.6691x; 1.1284x over previous
#include <cuda_runtime.h>
#include <cuda_fp16.h>
#include <cstdint>
#include <cstddef>

#define BATCH 256
#define SEQ   128
#define DM    1024
#define HS    1024

// fp16 scratch (device globals: allocation-guard-safe)
__device__ __half g_q16[(size_t)BATCH * SEQ * DM];
__device__ __half g_k16[(size_t)BATCH * SEQ * DM];
__device__ __half g_x16[(size_t)BATCH * SEQ * DM];
__device__ __half g_wq16[(size_t)DM * HS];
__device__ __half g_wk16[(size_t)DM * HS];
__device__ __half g_wvT16[(size_t)HS * DM];
__device__ __half g_MT16[(size_t)DM * DM];
__device__ __half g_T16[(size_t)BATCH * SEQ * HS];
__device__ __half g_vT16[(size_t)BATCH * HS * SEQ];

// ===========================================================================
// Helpers
// ===========================================================================
__device__ __forceinline__ uint32_t smem_u32(const void* p) {
    uint32_t a;
    asm("{ .reg .u64 t; cvta.to.shared.u64 t, %1; cvt.u32.u64 %0, t; }"
        : "=r"(a) : "l"(p));
    return a;
}

__device__ __forceinline__ void mma_f16(float* d, const uint32_t* a, const uint32_t* b) {
    asm volatile(
        "mma.sync.aligned.m16n8k16.row.col.f32.f16.f16.f32 "
        "{%0,%1,%2,%3}, {%4,%5,%6,%7}, {%8,%9}, {%0,%1,%2,%3};"
        : "+f"(d[0]), "+f"(d[1]), "+f"(d[2]), "+f"(d[3])
        : "r"(a[0]), "r"(a[1]), "r"(a[2]), "r"(a[3]), "r"(b[0]), "r"(b[1]));
}

__device__ __forceinline__ void ldsm_x4(uint32_t addr, uint32_t& r0, uint32_t& r1,
                                        uint32_t& r2, uint32_t& r3) {
    asm volatile("ldmatrix.sync.aligned.m8n8.x4.shared.b16 {%0,%1,%2,%3}, [%4];"
                 : "=r"(r0), "=r"(r1), "=r"(r2), "=r"(r3) : "r"(addr));
}

__device__ __forceinline__ void cp_async16(uint32_t dst_smem, const void* src) {
    asm volatile("cp.async.cg.shared.global [%0], [%1], 16;"
                 :: "r"(dst_smem), "l"(src));
}
__device__ __forceinline__ void cp_commit() {
    asm volatile("cp.async.commit_group;");
}
template <int N>
__device__ __forceinline__ void cp_wait() {
    asm volatile("cp.async.wait_group %0;" :: "n"(N));
}

// ===========================================================================
// Pre-pass: fp32 -> fp16 conversions
// ===========================================================================
__global__ __launch_bounds__(256) void cvt_big(const float* __restrict__ q,
                                               const float* __restrict__ k,
                                               const float* __restrict__ v)
{
    const float* src = (blockIdx.z == 0) ? q : (blockIdx.z == 1) ? k : v;
    __half* dst = (blockIdx.z == 0) ? g_q16 : (blockIdx.z == 1) ? g_k16 : g_x16;
    const size_t i = (size_t)blockIdx.x * 256 + threadIdx.x;
    const size_t stride = 2097152;
    #pragma unroll
    for (int j = 0; j < 4; j++) {
        size_t idx = i + (size_t)j * stride;
        float4 f = reinterpret_cast<const float4*>(src)[idx];
        reinterpret_cast<__half2*>(dst)[idx * 2 + 0] = __float22half2_rn(make_float2(f.x, f.y));
        reinterpret_cast<__half2*>(dst)[idx * 2 + 1] = __float22half2_rn(make_float2(f.z, f.w));
    }
}

__global__ __launch_bounds__(256) void cvt_w(const float* __restrict__ wq,
                                             const float* __restrict__ wk)
{
    const float* src = blockIdx.z ? wk : wq;
    __half* dst = blockIdx.z ? g_wk16 : g_wq16;
    const size_t i = (size_t)blockIdx.x * 256 + threadIdx.x;
    const size_t stride = 65536;
    #pragma unroll
    for (int j = 0; j < 4; j++) {
        size_t idx = i + (size_t)j * stride;
        float4 f = reinterpret_cast<const float4*>(src)[idx];
        reinterpret_cast<__half2*>(dst)[idx * 2 + 0] = __float22half2_rn(make_float2(f.x, f.y));
        reinterpret_cast<__half2*>(dst)[idx * 2 + 1] = __float22half2_rn(make_float2(f.z, f.w));
    }
}

__global__ __launch_bounds__(256) void trans_wv(const float* __restrict__ wv)
{
    __shared__ float t[32][33];
    const int tx = threadIdx.x & 31, ty = threadIdx.x >> 5;
    const int x0 = blockIdx.x * 32, y0 = blockIdx.y * 32;
    #pragma unroll
    for (int j = 0; j < 4; j++)
        t[ty + 8 * j][tx] = wv[(size_t)(y0 + ty + 8 * j) * HS + x0 + tx];
    __syncthreads();
    #pragma unroll
    for (int j = 0; j < 4; j++)
        g_wvT16[(size_t)(x0 + ty + 8 * j) * DM + y0 + tx] =
            __float2half_rn(t[tx][ty + 8 * j]);
}

// ===========================================================================
// fp16 NT GEMM body with ldmatrix fragment loads.
// C[m][n] = sum_k A[m][k]*B[n][k]; CTA 128x128, BK=16, 3-stage cp.async.
// ===========================================================================
#define PA 24
#define PB 24
#define AST (128 * PA)
#define BST (128 * PB)
#define STG_H (AST + BST)
#define NST 3
#define GEMM_SMEM (NST * STG_H * 2)

// ldmatrix address precompute (halfword offsets relative to tile base):
//  A x4 (mt tile): row = warp_m + mt*16 + (lane&15), koff = (lane>>4)*8
//  B x4 (nt pair p): tile t=lane>>3, nt=2p+(t>>1), koff=(t&1)*8, row j=lane&7
__device__ __forceinline__ void gemm_nt_f16(const __half* __restrict__ A,
                                            const __half* __restrict__ B,
                                            __half* __restrict__ C,
                                            __half* sm, uint32_t smb,
                                            int m0, int n0, int ldc)
{
    const int tid  = threadIdx.x;
    const int wid  = tid >> 5;
    const int lane = tid & 31;
    const int g    = lane >> 2;
    const int tg   = lane & 3;
    const int wm   = wid >> 1;
    const int wn   = wid & 1;
    const int row  = tid >> 1, hf = tid & 1;

    // per-thread ldmatrix offsets (in halfwords)
    const int a_off = (wm * 32 + (lane & 15)) * PA + (lane >> 4) * 8;
    const int b_off = (wn * 64 + ((lane >> 4) << 3) + (lane & 7)) * PB + ((lane >> 3) & 1) * 8;

    float acc[2][8][4];
    #pragma unroll
    for (int i = 0; i < 2; i++)
        #pragma unroll
        for (int j = 0; j < 8; j++)
            #pragma unroll
            for (int c = 0; c < 4; c++) acc[i][j][c] = 0.f;

    auto load_stage = [&](int ks, int buf) {
        const int k0 = ks * 16;
        const uint32_t sa = smb + (uint32_t)(buf * STG_H) * 2u;
        const uint32_t sb = sa + (uint32_t)AST * 2u;
        cp_async16(sa + row * 48 + hf * 16, A + (size_t)(m0 + row) * DM + k0 + hf * 8);
        cp_async16(sb + row * 48 + hf * 16, B + (size_t)(n0 + row) * DM + k0 + hf * 8);
    };

    load_stage(0, 0); cp_commit();
    load_stage(1, 1); cp_commit();

    for (int i = 0; i < 64; i++) {
        cp_wait<1>();
        __syncthreads();
        if (i + 2 < 64) load_stage(i + 2, (i + 2) % NST);
        cp_commit();

        const uint32_t As = smb + (uint32_t)((i % NST) * STG_H) * 2u;
        const uint32_t Bs = As + (uint32_t)AST * 2u;

        uint32_t a[2][4], bf[8][2];
        #pragma unroll
        for (int mt = 0; mt < 2; mt++)
            ldsm_x4(As + (uint32_t)(a_off + mt * 16 * PA) * 2u,
                    a[mt][0], a[mt][1], a[mt][2], a[mt][3]);
        #pragma unroll
        for (int p = 0; p < 4; p++)
            ldsm_x4(Bs + (uint32_t)(b_off + p * 16 * PB) * 2u,
                    bf[2 * p][0], bf[2 * p][1], bf[2 * p + 1][0], bf[2 * p + 1][1]);
        #pragma unroll
        for (int mt = 0; mt < 2; mt++)
            #pragma unroll
            for (int nt = 0; nt < 8; nt++)
                mma_f16(acc[mt][nt], a[mt], bf[nt]);
        __syncthreads();
    }

    #pragma unroll
    for (int mt = 0; mt < 2; mt++) {
        const int mrow = m0 + wm * 32 + mt * 16;
        #pragma unroll
        for (int nt = 0; nt < 8; nt++) {
            const int ncol = n0 + wn * 64 + nt * 8 + 2 * tg;
            *reinterpret_cast<__half2*>(C + (size_t)(mrow + g) * ldc + ncol) =
                __float22half2_rn(make_float2(acc[mt][nt][0], acc[mt][nt][1]));
            *reinterpret_cast<__half2*>(C + (size_t)(mrow + g + 8) * ldc + ncol) =
                __float22half2_rn(make_float2(acc[mt][nt][2], acc[mt][nt][3]));
        }
    }
}

__global__ __launch_bounds__(256, 2) void gemm_M()
{
    extern __shared__ __half sm[];
    gemm_nt_f16(g_wk16, g_wq16, g_MT16, sm, smem_u32(sm),
                blockIdx.y * 128, blockIdx.x * 128, DM);
}

__global__ __launch_bounds__(256, 2) void proj_f16()
{
    extern __shared__ __half sm[];
    const uint32_t smb = smem_u32(sm);
    if (blockIdx.z == 0) {
        gemm_nt_f16(g_q16, g_MT16, g_T16, sm, smb,
                    blockIdx.y * 128, blockIdx.x * 128, HS);
    } else {
        gemm_nt_f16(g_wvT16, g_x16 + (size_t)blockIdx.y * SEQ * DM,
                    g_vT16 + (size_t)blockIdx.y * HS * SEQ, sm, smb,
                    blockIdx.x * 128, 0, SEQ);
    }
}

// ===========================================================================
// Attention: one CTA per batch. S = T*key^T -> fp16 P -> softmax -> O = P*vT.
// ===========================================================================
#define PP 136
#define P_HW 12288
#define ATTN_SMEM ((P_HW + 128 * PP) * 2)

__global__ __launch_bounds__(256, 2) void attn_f16(float* __restrict__ O)
{
    extern __shared__ __half sm[];
    const uint32_t smb = smem_u32(sm);

    const int tid  = threadIdx.x;
    const int wid  = tid >> 5;
    const int lane = tid & 31;
    const int g    = lane >> 2;
    const int tg   = lane & 3;
    const int wm   = wid >> 1;
    const int wn   = wid & 1;
    const int row  = tid >> 1, hf = tid & 1;
    const int b    = blockIdx.x;

    const __half* Tb = g_T16 + (size_t)b * SEQ * HS;
    const __half* Kb = g_k16 + (size_t)b * SEQ * DM;
    const __half* Vb = g_vT16 + (size_t)b * HS * SEQ;
    __half* P = sm + P_HW;
    const uint32_t Pu = smb + (uint32_t)P_HW * 2u;

    const int a_off = (wm * 32 + (lane & 15)) * PA + (lane >> 4) * 8;
    const int b_off = (wn * 64 + ((lane >> 4) << 3) + (lane & 7)) * PB + ((lane >> 3) & 1) * 8;
    const int p_off = (wm * 32 + (lane & 15)) * PP + (lane >> 4) * 8;

    float acc[2][8][4];
    #pragma unroll
    for (int i = 0; i < 2; i++)
        #pragma unroll
        for (int j = 0; j < 8; j++)
            #pragma unroll
            for (int c = 0; c < 4; c++) acc[i][j][c] = 0.f;

    // ---------------- Phase 1: S = T K^T ----------------
    auto load_s = [&](int ks, int buf) {
        const int k0 = ks * 16;
        const uint32_t sa = smb + (uint32_t)(buf * STG_H) * 2u;
        const uint32_t sb = sa + (uint32_t)AST * 2u;
        cp_async16(sa + row * 48 + hf * 16, Tb + (size_t)row * HS + k0 + hf * 8);
        cp_async16(sb + row * 48 + hf * 16, Kb + (size_t)row * DM + k0 + hf * 8);
    };
    auto load_v = [&](int s) {
        const int ntile = s >> 3, ki = s & 7;
        const uint32_t sv = smb + (uint32_t)((s & 1) * BST) * 2u;
        cp_async16(sv + row * 48 + hf * 16,
                   Vb + (size_t)(ntile * 128 + row) * SEQ + ki * 16 + hf * 8);
    };

    load_s(0, 0); cp_commit();
    for (int i = 0; i < 64; i++) {
        if (i + 1 < 64) { load_s(i + 1, (i + 1) & 1); cp_commit(); cp_wait<1>(); }
        else            { cp_wait<0>(); }
        __syncthreads();
        const uint32_t As = smb + (uint32_t)((i & 1) * STG_H) * 2u;
        const uint32_t Bs = As + (uint32_t)AST * 2u;

        uint32_t a[2][4], bf[8][2];
        #pragma unroll
        for (int mt = 0; mt < 2; mt++)
            ldsm_x4(As + (uint32_t)(a_off + mt * 16 * PA) * 2u,
                    a[mt][0], a[mt][1], a[mt][2], a[mt][3]);
        #pragma unroll
        for (int p = 0; p < 4; p++)
            ldsm_x4(Bs + (uint32_t)(b_off + p * 16 * PB) * 2u,
                    bf[2 * p][0], bf[2 * p][1], bf[2 * p + 1][0], bf[2 * p + 1][1]);
        #pragma unroll
        for (int mt = 0; mt < 2; mt++)
            #pragma unroll
            for (int nt = 0; nt < 8; nt++)
                mma_f16(acc[mt][nt], a[mt], bf[nt]);
        __syncthreads();
    }

    load_v(0); cp_commit();   // prefetch V stage 0, overlaps softmax

    const float scale = 0.03125f;
    #pragma unroll
    for (int mt = 0; mt < 2; mt++) {
        const int mrow = wm * 32 + mt * 16;
        #pragma unroll
        for (int nt = 0; nt < 8; nt++) {
            const int ncol = wn * 64 + nt * 8 + 2 * tg;
            *reinterpret_cast<__half2*>(P + (mrow + g) * PP + ncol) =
                __float22half2_rn(make_float2(acc[mt][nt][0] * scale, acc[mt][nt][1] * scale));
            *reinterpret_cast<__half2*>(P + (mrow + g + 8) * PP + ncol) =
                __float22half2_rn(make_float2(acc[mt][nt][2] * scale, acc[mt][nt][3] * scale));
        }
    }
    __syncthreads();

    // ---------------- Phase 2: causal softmax (warp per row) ----------------
    #pragma unroll 1
    for (int i = 0; i < 16; i++) {
        const int r = wid * 16 + i;
        float x[4];
        #pragma unroll
        for (int j = 0; j < 4; j++) {
            const int col = lane + 32 * j;
            x[j] = (col <= r) ? __half2float(P[r * PP + col]) : -1e30f;
        }
        float m = fmaxf(fmaxf(x[0], x[1]), fmaxf(x[2], x[3]));
        #pragma unroll
        for (int o = 16; o > 0; o >>= 1) m = fmaxf(m, __shfl_xor_sync(0xffffffffu, m, o));
        float e[4], s = 0.f;
        #pragma unroll
        for (int j = 0; j < 4; j++) {
            const int col = lane + 32 * j;
            e[j] = (col <= r) ? __expf(x[j] - m) : 0.f;
            s += e[j];
        }
        #pragma unroll
        for (int o = 16; o > 0; o >>= 1) s += __shfl_xor_sync(0xffffffffu, s, o);
        const float inv = 1.f / s;
        #pragma unroll
        for (int j = 0; j < 4; j++)
            P[r * PP + lane + 32 * j] = __float2half_rn(e[j] * inv);
    }
    __syncthreads();

    // ---------------- Phase 3: O = P * vT ----------------
    for (int nt = 0; nt < 8; nt++) {
        #pragma unroll
        for (int i = 0; i < 2; i++)
            #pragma unroll
            for (int j = 0; j < 8; j++)
                #pragma unroll
                for (int c = 0; c < 4; c++) acc[i][j][c] = 0.f;

        for (int ki = 0; ki < 8; ki++) {
            const int s = nt * 8 + ki;
            if (s + 1 < 64) { load_v(s + 1); cp_commit(); cp_wait<1>(); }
            else            { cp_wait<0>(); }
            __syncthreads();
            const uint32_t Vs = smb + (uint32_t)((s & 1) * BST) * 2u;

            uint32_t a[2][4], bf[8][2];
            #pragma unroll
            for (int mt = 0; mt < 2; mt++)
                ldsm_x4(Pu + (uint32_t)(p_off + mt * 16 * PP + ki * 16) * 2u,
                        a[mt][0], a[mt][1], a[mt][2], a[mt][3]);
            #pragma unroll
            for (int p = 0; p < 4; p++)
                ldsm_x4(Vs + (uint32_t)(b_off + p * 16 * PB) * 2u,
                        bf[2 * p][0], bf[2 * p][1], bf[2 * p + 1][0], bf[2 * p + 1][1]);
            #pragma unroll
            for (int mt = 0; mt < 2; mt++)
                #pragma unroll
                for (int nt2 = 0; nt2 < 8; nt2++)
                    mma_f16(acc[mt][nt2], a[mt], bf[nt2]);
            __syncthreads();
        }

        #pragma unroll
        for (int mt = 0; mt < 2; mt++) {
            const int mrow = wm * 32 + mt * 16;
            #pragma unroll
            for (int nt2 = 0; nt2 < 8; nt2++) {
                const int ncol = nt * 128 + wn * 64 + nt2 * 8 + 2 * tg;
                *reinterpret_cast<float2*>(O + ((size_t)b * SEQ + mrow + g) * HS + ncol) =
                    make_float2(acc[mt][nt2][0], acc[mt][nt2][1]);
                *reinterpret_cast<float2*>(O + ((size_t)b * SEQ + mrow + g + 8) * HS + ncol) =
                    make_float2(acc[mt][nt2][2], acc[mt][nt2][3]);
            }
        }
    }
}

// ===========================================================================
extern "C" void kernel_launch(void* const* d_in, const int* in_sizes, int n_in,
                              void* d_out, int out_size)
{
    const float* query = (const float*)d_in[0];
    const float* key   = (const float*)d_in[1];
    const float* value = (const float*)d_in[2];
    const float* w_q   = (const float*)d_in[3];
    const float* w_k   = (const float*)d_in[4];
    const float* w_v   = (const float*)d_in[5];
    float* out = (float*)d_out;

    cvt_big<<<dim3(8192, 1, 3), 256>>>(query, key, value);
    cvt_w<<<dim3(256, 1, 2), 256>>>(w_q, w_k);
    trans_wv<<<dim3(32, 32), 256>>>(w_v);

    cudaFuncSetAttribute(gemm_M, cudaFuncAttributeMaxDynamicSharedMemorySize, GEMM_SMEM);
    gemm_M<<<dim3(8, 8), 256, GEMM_SMEM>>>();

    cudaFuncSetAttribute(proj_f16, cudaFuncAttributeMaxDynamicSharedMemorySize, GEMM_SMEM);
    proj_f16<<<dim3(8, 256, 2), 256, GEMM_SMEM>>>();

    cudaFuncSetAttribute(attn_f16, cudaFuncAttributeMaxDynamicSharedMemorySize, ATTN_SMEM);
    attn_f16<<<BATCH, 256, ATTN_SMEM>>>(out);
}

// round 9
// speedup vs baseline: 1.8712x; 1.1211x over previous
#include <cuda_runtime.h>
#include <cuda_fp16.h>
#include <cstdint>
#include <cstddef>

#define BATCH 256
#define SEQ   128
#define DM    1024
#define HS    1024

// fp16 scratch (device globals: allocation-guard-safe)
__device__ __half g_q16[(size_t)BATCH * SEQ * DM];
__device__ __half g_k16[(size_t)BATCH * SEQ * DM];
__device__ __half g_x16[(size_t)BATCH * SEQ * DM];
__device__ __half g_wq16[(size_t)DM * HS];
__device__ __half g_wk16[(size_t)DM * HS];
__device__ __half g_wvT16[(size_t)HS * DM];
__device__ __half g_MT16[(size_t)DM * DM];
__device__ __half g_T16[(size_t)BATCH * SEQ * HS];
__device__ __half g_vT16[(size_t)BATCH * HS * SEQ];

// ===========================================================================
// Helpers
// ===========================================================================
__device__ __forceinline__ uint32_t smem_u32(const void* p) {
    uint32_t a;
    asm("{ .reg .u64 t; cvta.to.shared.u64 t, %1; cvt.u32.u64 %0, t; }"
        : "=r"(a) : "l"(p));
    return a;
}

__device__ __forceinline__ void mma_f16(float* d, const uint32_t* a, const uint32_t* b) {
    asm volatile(
        "mma.sync.aligned.m16n8k16.row.col.f32.f16.f16.f32 "
        "{%0,%1,%2,%3}, {%4,%5,%6,%7}, {%8,%9}, {%0,%1,%2,%3};"
        : "+f"(d[0]), "+f"(d[1]), "+f"(d[2]), "+f"(d[3])
        : "r"(a[0]), "r"(a[1]), "r"(a[2]), "r"(a[3]), "r"(b[0]), "r"(b[1]));
}

__device__ __forceinline__ void ldsm_x4(uint32_t addr, uint32_t& r0, uint32_t& r1,
                                        uint32_t& r2, uint32_t& r3) {
    asm volatile("ldmatrix.sync.aligned.m8n8.x4.shared.b16 {%0,%1,%2,%3}, [%4];"
                 : "=r"(r0), "=r"(r1), "=r"(r2), "=r"(r3) : "r"(addr));
}

__device__ __forceinline__ void cp_async16(uint32_t dst_smem, const void* src) {
    asm volatile("cp.async.cg.shared.global [%0], [%1], 16;"
                 :: "r"(dst_smem), "l"(src));
}
__device__ __forceinline__ void cp_commit() {
    asm volatile("cp.async.commit_group;");
}
template <int N>
__device__ __forceinline__ void cp_wait() {
    asm volatile("cp.async.wait_group %0;" :: "n"(N));
}

// ===========================================================================
// Single fused pre-pass launch. grid (8192, 1, 6).
//  z=0,1,2: q/k/v fp32->fp16 ; z=3,4: w_q/w_k cvt ; z=5: W_v transpose+cvt
// ===========================================================================
__global__ __launch_bounds__(256) void prepass(const float* __restrict__ q,
                                               const float* __restrict__ k,
                                               const float* __restrict__ v,
                                               const float* __restrict__ wq,
                                               const float* __restrict__ wk,
                                               const float* __restrict__ wv)
{
    const int z = blockIdx.z;
    if (z < 3) {
        const float* src = (z == 0) ? q : (z == 1) ? k : v;
        __half* dst = (z == 0) ? g_q16 : (z == 1) ? g_k16 : g_x16;
        const size_t i = (size_t)blockIdx.x * 256 + threadIdx.x;
        const size_t stride = 2097152;
        #pragma unroll
        for (int j = 0; j < 4; j++) {
            size_t idx = i + (size_t)j * stride;
            float4 f = reinterpret_cast<const float4*>(src)[idx];
            reinterpret_cast<__half2*>(dst)[idx * 2 + 0] = __float22half2_rn(make_float2(f.x, f.y));
            reinterpret_cast<__half2*>(dst)[idx * 2 + 1] = __float22half2_rn(make_float2(f.z, f.w));
        }
    } else if (z < 5) {
        if (blockIdx.x >= 256) return;
        const float* src = (z == 4) ? wk : wq;
        __half* dst = (z == 4) ? g_wk16 : g_wq16;
        const size_t i = (size_t)blockIdx.x * 256 + threadIdx.x;
        const size_t stride = 65536;
        #pragma unroll
        for (int j = 0; j < 4; j++) {
            size_t idx = i + (size_t)j * stride;
            float4 f = reinterpret_cast<const float4*>(src)[idx];
            reinterpret_cast<__half2*>(dst)[idx * 2 + 0] = __float22half2_rn(make_float2(f.x, f.y));
            reinterpret_cast<__half2*>(dst)[idx * 2 + 1] = __float22half2_rn(make_float2(f.z, f.w));
        }
    } else {
        if (blockIdx.x >= 1024) return;
        __shared__ float t[32][33];
        const int tx = threadIdx.x & 31, ty = threadIdx.x >> 5;
        const int x0 = (blockIdx.x & 31) * 32, y0 = (blockIdx.x >> 5) * 32;
        #pragma unroll
        for (int j = 0; j < 4; j++)
            t[ty + 8 * j][tx] = wv[(size_t)(y0 + ty + 8 * j) * HS + x0 + tx];
        __syncthreads();
        #pragma unroll
        for (int j = 0; j < 4; j++)
            g_wvT16[(size_t)(x0 + ty + 8 * j) * DM + y0 + tx] =
                __float2half_rn(t[tx][ty + 8 * j]);
    }
}

// ===========================================================================
// fp16 NT GEMM body: C[m][n] = sum_k A[m][k]*B[n][k].
// CTA 128x128, BK=32, 3-stage cp.async, ONE sync per iteration.
// Pitch 40 hw: ldmatrix banks (20r)%32 hit all 32 banks -> conflict-free.
// ===========================================================================
#define PA 40
#define AST (128 * PA)            // 5120 hw per A stage
#define STG_H (2 * AST)           // 10240 hw per stage (A+B)
#define NST 3
#define GEMM_SMEM (NST * STG_H * 2)   // 61440 B

__device__ __forceinline__ void gemm_nt_f16(const __half* __restrict__ A,
                                            const __half* __restrict__ B,
                                            __half* __restrict__ C,
                                            uint32_t smb,
                                            int m0, int n0, int ldc)
{
    const int tid  = threadIdx.x;
    const int wid  = tid >> 5;
    const int lane = tid & 31;
    const int g    = lane >> 2;
    const int tg   = lane & 3;
    const int wm   = wid >> 1;
    const int wn   = wid & 1;

    const int a_off = (wm * 32 + (lane & 15)) * PA + (lane >> 4) * 8;
    const int b_off = (wn * 64 + ((lane >> 4) << 3) + (lane & 7)) * PA + ((lane >> 3) & 1) * 8;
    const int r0 = tid >> 2, q0 = tid & 3;
    const int r1 = (tid + 256) >> 2;

    float acc[2][8][4];
    #pragma unroll
    for (int i = 0; i < 2; i++)
        #pragma unroll
        for (int j = 0; j < 8; j++)
            #pragma unroll
            for (int c = 0; c < 4; c++) acc[i][j][c] = 0.f;

    auto load_stage = [&](int ks, int buf) {
        const int k0 = ks * 32;
        const uint32_t sa = smb + (uint32_t)(buf * STG_H) * 2u;
        const uint32_t sb = sa + (uint32_t)AST * 2u;
        cp_async16(sa + r0 * 80 + q0 * 16, A + (size_t)(m0 + r0) * DM + k0 + q0 * 8);
        cp_async16(sa + r1 * 80 + q0 * 16, A + (size_t)(m0 + r1) * DM + k0 + q0 * 8);
        cp_async16(sb + r0 * 80 + q0 * 16, B + (size_t)(n0 + r0) * DM + k0 + q0 * 8);
        cp_async16(sb + r1 * 80 + q0 * 16, B + (size_t)(n0 + r1) * DM + k0 + q0 * 8);
    };

    load_stage(0, 0); cp_commit();
    load_stage(1, 1); cp_commit();

    for (int i = 0; i < 32; i++) {
        cp_wait<1>();
        __syncthreads();
        if (i + 2 < 32) load_stage(i + 2, (i + 2) % NST);
        cp_commit();

        const uint32_t As = smb + (uint32_t)((i % NST) * STG_H) * 2u;
        const uint32_t Bs = As + (uint32_t)AST * 2u;

        #pragma unroll
        for (int j = 0; j < 2; j++) {
            uint32_t a[2][4], bf[8][2];
            #pragma unroll
            for (int mt = 0; mt < 2; mt++)
                ldsm_x4(As + (uint32_t)(a_off + j * 16 + mt * 16 * PA) * 2u,
                        a[mt][0], a[mt][1], a[mt][2], a[mt][3]);
            #pragma unroll
            for (int p = 0; p < 4; p++)
                ldsm_x4(Bs + (uint32_t)(b_off + j * 16 + p * 16 * PA) * 2u,
                        bf[2 * p][0], bf[2 * p][1], bf[2 * p + 1][0], bf[2 * p + 1][1]);
            #pragma unroll
            for (int mt = 0; mt < 2; mt++)
                #pragma unroll
                for (int nt = 0; nt < 8; nt++)
                    mma_f16(acc[mt][nt], a[mt], bf[nt]);
        }
    }

    #pragma unroll
    for (int mt = 0; mt < 2; mt++) {
        const int mrow = m0 + wm * 32 + mt * 16;
        #pragma unroll
        for (int nt = 0; nt < 8; nt++) {
            const int ncol = n0 + wn * 64 + nt * 8 + 2 * tg;
            *reinterpret_cast<__half2*>(C + (size_t)(mrow + g) * ldc + ncol) =
                __float22half2_rn(make_float2(acc[mt][nt][0], acc[mt][nt][1]));
            *reinterpret_cast<__half2*>(C + (size_t)(mrow + g + 8) * ldc + ncol) =
                __float22half2_rn(make_float2(acc[mt][nt][2], acc[mt][nt][3]));
        }
    }
}

__global__ __launch_bounds__(256, 2) void gemm_M()
{
    extern __shared__ __half sm[];
    gemm_nt_f16(g_wk16, g_wq16, g_MT16, smem_u32(sm),
                blockIdx.y * 128, blockIdx.x * 128, DM);
}

__global__ __launch_bounds__(256, 2) void proj_f16()
{
    extern __shared__ __half sm[];
    const uint32_t smb = smem_u32(sm);
    if (blockIdx.z == 0) {
        gemm_nt_f16(g_q16, g_MT16, g_T16, smb,
                    blockIdx.y * 128, blockIdx.x * 128, HS);
    } else {
        gemm_nt_f16(g_wvT16, g_x16 + (size_t)blockIdx.y * SEQ * DM,
                    g_vT16 + (size_t)blockIdx.y * HS * SEQ, smb,
                    blockIdx.x * 128, 0, SEQ);
    }
}

// ===========================================================================
// Attention: one CTA per batch. S = T*key^T (causal-skipped) -> fp16 P ->
// softmax -> O = P*vT (structural-zero k-chunks skipped).
// SMEM (hw): [0, 3*STG_H) phase-1 stages (V stages alias front), then P.
// ===========================================================================
#define PP 136
#define PV 24
#define VST (128 * PV)            // 3072 hw per V stage
#define P_HW (NST * STG_H)        // 30720
#define ATTN_SMEM ((P_HW + 128 * PP) * 2)   // 96256 B

__global__ __launch_bounds__(256, 2) void attn_f16(float* __restrict__ O)
{
    extern __shared__ __half sm[];
    const uint32_t smb = smem_u32(sm);

    const int tid  = threadIdx.x;
    const int wid  = tid >> 5;
    const int lane = tid & 31;
    const int g    = lane >> 2;
    const int tg   = lane & 3;
    const int wm   = wid >> 1;
    const int wn   = wid & 1;
    const int b    = blockIdx.x;

    const __half* Tb = g_T16 + (size_t)b * SEQ * HS;
    const __half* Kb = g_k16 + (size_t)b * SEQ * DM;
    const __half* Vb = g_vT16 + (size_t)b * HS * SEQ;
    __half* P = sm + P_HW;
    const uint32_t Pu = smb + (uint32_t)P_HW * 2u;

    const int a_off  = (wm * 32 + (lane & 15)) * PA + (lane >> 4) * 8;
    const int b_off  = (wn * 64 + ((lane >> 4) << 3) + (lane & 7)) * PA + ((lane >> 3) & 1) * 8;
    const int bv_off = (wn * 64 + ((lane >> 4) << 3) + (lane & 7)) * PV + ((lane >> 3) & 1) * 8;
    const int p_off  = (wm * 32 + (lane & 15)) * PP + (lane >> 4) * 8;

    const int r0 = tid >> 2, q0 = tid & 3;
    const int r1 = (tid + 256) >> 2;
    const int vr = tid >> 1, vh = tid & 1;

    float acc[2][8][4];
    #pragma unroll
    for (int i = 0; i < 2; i++)
        #pragma unroll
        for (int j = 0; j < 8; j++)
            #pragma unroll
            for (int c = 0; c < 4; c++) acc[i][j][c] = 0.f;

    // ---------------- Phase 1: S = T K^T (BK=32, 3-stage, causal skip) -----
    auto load_s = [&](int ks, int buf) {
        const int k0 = ks * 32;
        const uint32_t sa = smb + (uint32_t)(buf * STG_H) * 2u;
        const uint32_t sb = sa + (uint32_t)AST * 2u;
        cp_async16(sa + r0 * 80 + q0 * 16, Tb + (size_t)r0 * HS + k0 + q0 * 8);
        cp_async16(sa + r1 * 80 + q0 * 16, Tb + (size_t)r1 * HS + k0 + q0 * 8);
        cp_async16(sb + r0 * 80 + q0 * 16, Kb + (size_t)r0 * DM + k0 + q0 * 8);
        cp_async16(sb + r1 * 80 + q0 * 16, Kb + (size_t)r1 * DM + k0 + q0 * 8);
    };
    auto load_v = [&](int s) {
        const int ntile = s >> 3, ki = s & 7;
        const uint32_t sv = smb + (uint32_t)((s & 1) * VST) * 2u;
        cp_async16(sv + vr * 48 + vh * 16,
                   Vb + (size_t)(ntile * 128 + vr) * SEQ + ki * 16 + vh * 8);
    };

    load_s(0, 0); cp_commit();
    load_s(1, 1); cp_commit();

    for (int i = 0; i < 32; i++) {
        cp_wait<1>();
        __syncthreads();
        if (i + 2 < 32) load_s(i + 2, (i + 2) % NST);
        cp_commit();

        const uint32_t As = smb + (uint32_t)((i % NST) * STG_H) * 2u;
        const uint32_t Bs = As + (uint32_t)AST * 2u;

        #pragma unroll
        for (int j = 0; j < 2; j++) {
            uint32_t a[2][4], bf[8][2];
            #pragma unroll
            for (int mt = 0; mt < 2; mt++)
                ldsm_x4(As + (uint32_t)(a_off + j * 16 + mt * 16 * PA) * 2u,
                        a[mt][0], a[mt][1], a[mt][2], a[mt][3]);
            #pragma unroll
            for (int p = 0; p < 4; p++)
                ldsm_x4(Bs + (uint32_t)(b_off + j * 16 + p * 16 * PA) * 2u,
                        bf[2 * p][0], bf[2 * p][1], bf[2 * p + 1][0], bf[2 * p + 1][1]);
            #pragma unroll
            for (int mt = 0; mt < 2; mt++)
                #pragma unroll
                for (int nt = 0; nt < 8; nt++)
                    if (wn * 64 + nt * 8 <= wm * 32 + mt * 16 + 15)   // causal skip
                        mma_f16(acc[mt][nt], a[mt], bf[nt]);
        }
    }

    load_v(0); cp_commit();   // prefetch V stage 0, overlaps softmax

    const float scale = 0.03125f;
    #pragma unroll
    for (int mt = 0; mt < 2; mt++) {
        const int mrow = wm * 32 + mt * 16;
        #pragma unroll
        for (int nt = 0; nt < 8; nt++) {
            const int ncol = wn * 64 + nt * 8 + 2 * tg;
            *reinterpret_cast<__half2*>(P + (mrow + g) * PP + ncol) =
                __float22half2_rn(make_float2(acc[mt][nt][0] * scale, acc[mt][nt][1] * scale));
            *reinterpret_cast<__half2*>(P + (mrow + g + 8) * PP + ncol) =
                __float22half2_rn(make_float2(acc[mt][nt][2] * scale, acc[mt][nt][3] * scale));
        }
    }
    __syncthreads();

    // ---------------- Phase 2: causal softmax (warp per row) ----------------
    #pragma unroll 1
    for (int i = 0; i < 16; i++) {
        const int r = wid * 16 + i;
        float x[4];
        #pragma unroll
        for (int j = 0; j < 4; j++) {
            const int col = lane + 32 * j;
            x[j] = (col <= r) ? __half2float(P[r * PP + col]) : -1e30f;
        }
        float m = fmaxf(fmaxf(x[0], x[1]), fmaxf(x[2], x[3]));
        #pragma unroll
        for (int o = 16; o > 0; o >>= 1) m = fmaxf(m, __shfl_xor_sync(0xffffffffu, m, o));
        float e[4], s = 0.f;
        #pragma unroll
        for (int j = 0; j < 4; j++) {
            const int col = lane + 32 * j;
            e[j] = (col <= r) ? __expf(x[j] - m) : 0.f;
            s += e[j];
        }
        #pragma unroll
        for (int o = 16; o > 0; o >>= 1) s += __shfl_xor_sync(0xffffffffu, s, o);
        const float inv = 1.f / s;
        #pragma unroll
        for (int j = 0; j < 4; j++)
            P[r * PP + lane + 32 * j] = __float2half_rn(e[j] * inv);
    }
    __syncthreads();

    // ---------------- Phase 3: O = P * vT (structural-zero skip) -----------
    for (int nt = 0; nt < 8; nt++) {
        #pragma unroll
        for (int i = 0; i < 2; i++)
            #pragma unroll
            for (int j = 0; j < 8; j++)
                #pragma unroll
                for (int c = 0; c < 4; c++) acc[i][j][c] = 0.f;

        for (int ki = 0; ki < 8; ki++) {
            const int s = nt * 8 + ki;
            if (s + 1 < 64) { load_v(s + 1); cp_commit(); cp_wait<1>(); }
            else            { cp_wait<0>(); }
            __syncthreads();
            const uint32_t Vs = smb + (uint32_t)((s & 1) * VST) * 2u;

            // P[m][k] == 0 for k > m: skip chunks entirely past this warp's rows
            const bool act1 = (ki * 16 <= wm * 32 + 31);               // mt=1 tile
            const bool act0 = (ki * 16 <= wm * 32 + 15);               // mt=0 tile
            if (act1) {
                uint32_t a[2][4], bf[8][2];
                ldsm_x4(Pu + (uint32_t)(p_off + 16 * PP + ki * 16) * 2u,
                        a[1][0], a[1][1], a[1][2], a[1][3]);
                if (act0)
                    ldsm_x4(Pu + (uint32_t)(p_off + ki * 16) * 2u,
                            a[0][0], a[0][1], a[0][2], a[0][3]);
                #pragma unroll
                for (int p = 0; p < 4; p++)
                    ldsm_x4(Vs + (uint32_t)(bv_off + p * 16 * PV) * 2u,
                            bf[2 * p][0], bf[2 * p][1], bf[2 * p + 1][0], bf[2 * p + 1][1]);
                #pragma unroll
                for (int nt2 = 0; nt2 < 8; nt2++) {
                    mma_f16(acc[1][nt2], a[1], bf[nt2]);
                    if (act0) mma_f16(acc[0][nt2], a[0], bf[nt2]);
                }
            }
            __syncthreads();
        }

        #pragma unroll
        for (int mt = 0; mt < 2; mt++) {
            const int mrow = wm * 32 + mt * 16;
            #pragma unroll
            for (int nt2 = 0; nt2 < 8; nt2++) {
                const int ncol = nt * 128 + wn * 64 + nt2 * 8 + 2 * tg;
                *reinterpret_cast<float2*>(O + ((size_t)b * SEQ + mrow + g) * HS + ncol) =
                    make_float2(acc[mt][nt2][0], acc[mt][nt2][1]);
                *reinterpret_cast<float2*>(O + ((size_t)b * SEQ + mrow + g + 8) * HS + ncol) =
                    make_float2(acc[mt][nt2][2], acc[mt][nt2][3]);
            }
        }
    }
}

// ===========================================================================
extern "C" void kernel_launch(void* const* d_in, const int* in_sizes, int n_in,
                              void* d_out, int out_size)
{
    const float* query = (const float*)d_in[0];
    const float* key   = (const float*)d_in[1];
    const float* value = (const float*)d_in[2];
    const float* w_q   = (const float*)d_in[3];
    const float* w_k   = (const float*)d_in[4];
    const float* w_v   = (const float*)d_in[5];
    float* out = (float*)d_out;

    prepass<<<dim3(8192, 1, 6), 256>>>(query, key, value, w_q, w_k, w_v);

    cudaFuncSetAttribute(gemm_M, cudaFuncAttributeMaxDynamicSharedMemorySize, GEMM_SMEM);
    gemm_M<<<dim3(8, 8), 256, GEMM_SMEM>>>();

    cudaFuncSetAttribute(proj_f16, cudaFuncAttributeMaxDynamicSharedMemorySize, GEMM_SMEM);
    proj_f16<<<dim3(8, 256, 2), 256, GEMM_SMEM>>>();

    cudaFuncSetAttribute(attn_f16, cudaFuncAttributeMaxDynamicSharedMemorySize, ATTN_SMEM);
    attn_f16<<<BATCH, 256, ATTN_SMEM>>>(out);
}

// round 10
// speedup vs baseline: 2.0001x; 1.0689x over previous
#include <cuda_runtime.h>
#include <cuda_fp16.h>
#include <cstdint>
#include <cstddef>

#define BATCH 256
#define SEQ   128
#define DM    1024
#define HS    1024

// fp16 scratch (device globals: allocation-guard-safe)
__device__ __half g_q16[(size_t)BATCH * SEQ * DM];
__device__ __half g_k16[(size_t)BATCH * SEQ * DM];
__device__ __half g_x16[(size_t)BATCH * SEQ * DM];
__device__ __half g_wq16[(size_t)DM * HS];
__device__ __half g_wk16[(size_t)DM * HS];
__device__ __half g_wvT16[(size_t)HS * DM];
__device__ __half g_MT16[(size_t)DM * DM];
__device__ __half g_T16[(size_t)BATCH * SEQ * HS];
__device__ __half g_vT16[(size_t)BATCH * HS * SEQ];

// ===========================================================================
// Helpers
// ===========================================================================
__device__ __forceinline__ uint32_t smem_u32(const void* p) {
    uint32_t a;
    asm("{ .reg .u64 t; cvta.to.shared.u64 t, %1; cvt.u32.u64 %0, t; }"
        : "=r"(a) : "l"(p));
    return a;
}

__device__ __forceinline__ void mma_f16(float* d, const uint32_t* a, const uint32_t* b) {
    asm volatile(
        "mma.sync.aligned.m16n8k16.row.col.f32.f16.f16.f32 "
        "{%0,%1,%2,%3}, {%4,%5,%6,%7}, {%8,%9}, {%0,%1,%2,%3};"
        : "+f"(d[0]), "+f"(d[1]), "+f"(d[2]), "+f"(d[3])
        : "r"(a[0]), "r"(a[1]), "r"(a[2]), "r"(a[3]), "r"(b[0]), "r"(b[1]));
}

__device__ __forceinline__ void ldsm_x4(uint32_t addr, uint32_t& r0, uint32_t& r1,
                                        uint32_t& r2, uint32_t& r3) {
    asm volatile("ldmatrix.sync.aligned.m8n8.x4.shared.b16 {%0,%1,%2,%3}, [%4];"
                 : "=r"(r0), "=r"(r1), "=r"(r2), "=r"(r3) : "r"(addr));
}

__device__ __forceinline__ void cp_async16(uint32_t dst_smem, const void* src) {
    asm volatile("cp.async.cg.shared.global [%0], [%1], 16;"
                 :: "r"(dst_smem), "l"(src));
}
__device__ __forceinline__ void cp_commit() {
    asm volatile("cp.async.commit_group;");
}
template <int N>
__device__ __forceinline__ void cp_wait() {
    asm volatile("cp.async.wait_group %0;" :: "n"(N));
}

// ===========================================================================
// Single fused pre-pass launch. grid (8192, 1, 6), 256 threads.
// ===========================================================================
__global__ __launch_bounds__(256) void prepass(const float* __restrict__ q,
                                               const float* __restrict__ k,
                                               const float* __restrict__ v,
                                               const float* __restrict__ wq,
                                               const float* __restrict__ wk,
                                               const float* __restrict__ wv)
{
    const int z = blockIdx.z;
    if (z < 3) {
        const float* src = (z == 0) ? q : (z == 1) ? k : v;
        __half* dst = (z == 0) ? g_q16 : (z == 1) ? g_k16 : g_x16;
        const size_t i = (size_t)blockIdx.x * 256 + threadIdx.x;
        const size_t stride = 2097152;
        #pragma unroll
        for (int j = 0; j < 4; j++) {
            size_t idx = i + (size_t)j * stride;
            float4 f = reinterpret_cast<const float4*>(src)[idx];
            reinterpret_cast<__half2*>(dst)[idx * 2 + 0] = __float22half2_rn(make_float2(f.x, f.y));
            reinterpret_cast<__half2*>(dst)[idx * 2 + 1] = __float22half2_rn(make_float2(f.z, f.w));
        }
    } else if (z < 5) {
        if (blockIdx.x >= 256) return;
        const float* src = (z == 4) ? wk : wq;
        __half* dst = (z == 4) ? g_wk16 : g_wq16;
        const size_t i = (size_t)blockIdx.x * 256 + threadIdx.x;
        const size_t stride = 65536;
        #pragma unroll
        for (int j = 0; j < 4; j++) {
            size_t idx = i + (size_t)j * stride;
            float4 f = reinterpret_cast<const float4*>(src)[idx];
            reinterpret_cast<__half2*>(dst)[idx * 2 + 0] = __float22half2_rn(make_float2(f.x, f.y));
            reinterpret_cast<__half2*>(dst)[idx * 2 + 1] = __float22half2_rn(make_float2(f.z, f.w));
        }
    } else {
        if (blockIdx.x >= 1024) return;
        __shared__ float t[32][33];
        const int tx = threadIdx.x & 31, ty = threadIdx.x >> 5;
        const int x0 = (blockIdx.x & 31) * 32, y0 = (blockIdx.x >> 5) * 32;
        #pragma unroll
        for (int j = 0; j < 4; j++)
            t[ty + 8 * j][tx] = wv[(size_t)(y0 + ty + 8 * j) * HS + x0 + tx];
        __syncthreads();
        #pragma unroll
        for (int j = 0; j < 4; j++)
            g_wvT16[(size_t)(x0 + ty + 8 * j) * DM + y0 + tx] =
                __float2half_rn(t[tx][ty + 8 * j]);
    }
}

// ===========================================================================
// fp16 NT GEMM: C[m][n] = sum_k A[m][k]*B[n][k].
// CTA 128x128, 128 threads (4 warps), warp tile 64x64 (4 m-tiles x 8 n-tiles).
// BK=32, 3-stage cp.async, one sync per iteration. Pitch 40 hw: conflict-free.
// ===========================================================================
#define PA 40
#define AST (128 * PA)            // 5120 hw per A stage
#define STG_H (2 * AST)           // 10240 hw per stage (A+B)
#define NST 3
#define GEMM_SMEM (NST * STG_H * 2)   // 61440 B

__device__ __forceinline__ void gemm_nt_f16(const __half* __restrict__ A,
                                            const __half* __restrict__ B,
                                            __half* __restrict__ C,
                                            uint32_t smb,
                                            int m0, int n0, int ldc)
{
    const int tid  = threadIdx.x;
    const int wid  = tid >> 5;
    const int lane = tid & 31;
    const int g    = lane >> 2;
    const int tg   = lane & 3;
    const int wm   = wid >> 1;    // 0..1 (m block of 64)
    const int wn   = wid & 1;     // 0..1 (n block of 64)

    const int a_off = (wm * 64 + (lane & 15)) * PA + (lane >> 4) * 8;
    const int b_off = (wn * 64 + ((lane >> 4) << 3) + (lane & 7)) * PA + ((lane >> 3) & 1) * 8;
    const int r0 = tid >> 2, q0 = tid & 3;

    float acc[4][8][4];
    #pragma unroll
    for (int i = 0; i < 4; i++)
        #pragma unroll
        for (int j = 0; j < 8; j++)
            #pragma unroll
            for (int c = 0; c < 4; c++) acc[i][j][c] = 0.f;

    auto load_stage = [&](int ks, int buf) {
        const int k0 = ks * 32;
        const uint32_t sa = smb + (uint32_t)(buf * STG_H) * 2u;
        const uint32_t sb = sa + (uint32_t)AST * 2u;
        #pragma unroll
        for (int l = 0; l < 4; l++) {
            const int r = r0 + l * 32;
            cp_async16(sa + r * 80 + q0 * 16, A + (size_t)(m0 + r) * DM + k0 + q0 * 8);
            cp_async16(sb + r * 80 + q0 * 16, B + (size_t)(n0 + r) * DM + k0 + q0 * 8);
        }
    };

    load_stage(0, 0); cp_commit();
    load_stage(1, 1); cp_commit();

    for (int i = 0; i < 32; i++) {
        cp_wait<1>();
        __syncthreads();
        if (i + 2 < 32) load_stage(i + 2, (i + 2) % NST);
        cp_commit();

        const uint32_t As = smb + (uint32_t)((i % NST) * STG_H) * 2u;
        const uint32_t Bs = As + (uint32_t)AST * 2u;

        #pragma unroll
        for (int j = 0; j < 2; j++) {
            uint32_t a[4][4], bf[8][2];
            #pragma unroll
            for (int mt = 0; mt < 4; mt++)
                ldsm_x4(As + (uint32_t)(a_off + j * 16 + mt * 16 * PA) * 2u,
                        a[mt][0], a[mt][1], a[mt][2], a[mt][3]);
            #pragma unroll
            for (int p = 0; p < 4; p++)
                ldsm_x4(Bs + (uint32_t)(b_off + j * 16 + p * 16 * PA) * 2u,
                        bf[2 * p][0], bf[2 * p][1], bf[2 * p + 1][0], bf[2 * p + 1][1]);
            #pragma unroll
            for (int mt = 0; mt < 4; mt++)
                #pragma unroll
                for (int nt = 0; nt < 8; nt++)
                    mma_f16(acc[mt][nt], a[mt], bf[nt]);
        }
    }

    #pragma unroll
    for (int mt = 0; mt < 4; mt++) {
        const int mrow = m0 + wm * 64 + mt * 16;
        #pragma unroll
        for (int nt = 0; nt < 8; nt++) {
            const int ncol = n0 + wn * 64 + nt * 8 + 2 * tg;
            *reinterpret_cast<__half2*>(C + (size_t)(mrow + g) * ldc + ncol) =
                __float22half2_rn(make_float2(acc[mt][nt][0], acc[mt][nt][1]));
            *reinterpret_cast<__half2*>(C + (size_t)(mrow + g + 8) * ldc + ncol) =
                __float22half2_rn(make_float2(acc[mt][nt][2], acc[mt][nt][3]));
        }
    }
}

__global__ __launch_bounds__(128, 2) void gemm_M()
{
    extern __shared__ __half sm[];
    gemm_nt_f16(g_wk16, g_wq16, g_MT16, smem_u32(sm),
                blockIdx.y * 128, blockIdx.x * 128, DM);
}

__global__ __launch_bounds__(128, 2) void proj_f16()
{
    extern __shared__ __half sm[];
    const uint32_t smb = smem_u32(sm);
    if (blockIdx.z == 0) {
        gemm_nt_f16(g_q16, g_MT16, g_T16, smb,
                    blockIdx.y * 128, blockIdx.x * 128, HS);
    } else {
        gemm_nt_f16(g_wvT16, g_x16 + (size_t)blockIdx.y * SEQ * DM,
                    g_vT16 + (size_t)blockIdx.y * HS * SEQ, smb,
                    blockIdx.x * 128, 0, SEQ);
    }
}

// ===========================================================================
// Attention: one CTA per batch, 128 threads (4 warps), warp tile 64x64.
// S = T*key^T (causal skip) -> fp16 P -> softmax -> O = P*vT (zero-chunk skip).
// ===========================================================================
#define PP 136
#define PV 24
#define VST (128 * PV)            // 3072 hw per V stage
#define P_HW (NST * STG_H)        // 30720
#define ATTN_SMEM ((P_HW + 128 * PP) * 2)   // 96256 B

__global__ __launch_bounds__(128, 2) void attn_f16(float* __restrict__ O)
{
    extern __shared__ __half sm[];
    const uint32_t smb = smem_u32(sm);

    const int tid  = threadIdx.x;
    const int wid  = tid >> 5;
    const int lane = tid & 31;
    const int g    = lane >> 2;
    const int tg   = lane & 3;
    const int wm   = wid >> 1;
    const int wn   = wid & 1;
    const int b    = blockIdx.x;

    const __half* Tb = g_T16 + (size_t)b * SEQ * HS;
    const __half* Kb = g_k16 + (size_t)b * SEQ * DM;
    const __half* Vb = g_vT16 + (size_t)b * HS * SEQ;
    __half* P = sm + P_HW;
    const uint32_t Pu = smb + (uint32_t)P_HW * 2u;

    const int a_off  = (wm * 64 + (lane & 15)) * PA + (lane >> 4) * 8;
    const int b_off  = (wn * 64 + ((lane >> 4) << 3) + (lane & 7)) * PA + ((lane >> 3) & 1) * 8;
    const int bv_off = (wn * 64 + ((lane >> 4) << 3) + (lane & 7)) * PV + ((lane >> 3) & 1) * 8;
    const int p_off  = (wm * 64 + (lane & 15)) * PP + (lane >> 4) * 8;

    const int r0 = tid >> 2, q0 = tid & 3;
    const int vh = tid & 1, vr0 = tid >> 1;

    float acc[4][8][4];
    #pragma unroll
    for (int i = 0; i < 4; i++)
        #pragma unroll
        for (int j = 0; j < 8; j++)
            #pragma unroll
            for (int c = 0; c < 4; c++) acc[i][j][c] = 0.f;

    // ---------------- Phase 1: S = T K^T (BK=32, 3-stage, causal skip) -----
    auto load_s = [&](int ks, int buf) {
        const int k0 = ks * 32;
        const uint32_t sa = smb + (uint32_t)(buf * STG_H) * 2u;
        const uint32_t sb = sa + (uint32_t)AST * 2u;
        #pragma unroll
        for (int l = 0; l < 4; l++) {
            const int r = r0 + l * 32;
            cp_async16(sa + r * 80 + q0 * 16, Tb + (size_t)r * HS + k0 + q0 * 8);
            cp_async16(sb + r * 80 + q0 * 16, Kb + (size_t)r * DM + k0 + q0 * 8);
        }
    };
    auto load_v = [&](int s) {
        const int ntile = s >> 3, ki = s & 7;
        const uint32_t sv = smb + (uint32_t)((s & 1) * VST) * 2u;
        #pragma unroll
        for (int l = 0; l < 2; l++) {
            const int r = vr0 + l * 64;
            cp_async16(sv + r * 48 + vh * 16,
                       Vb + (size_t)(ntile * 128 + r) * SEQ + ki * 16 + vh * 8);
        }
    };

    load_s(0, 0); cp_commit();
    load_s(1, 1); cp_commit();

    for (int i = 0; i < 32; i++) {
        cp_wait<1>();
        __syncthreads();
        if (i + 2 < 32) load_s(i + 2, (i + 2) % NST);
        cp_commit();

        const uint32_t As = smb + (uint32_t)((i % NST) * STG_H) * 2u;
        const uint32_t Bs = As + (uint32_t)AST * 2u;

        #pragma unroll
        for (int j = 0; j < 2; j++) {
            uint32_t a[4][4], bf[8][2];
            #pragma unroll
            for (int mt = 0; mt < 4; mt++)
                ldsm_x4(As + (uint32_t)(a_off + j * 16 + mt * 16 * PA) * 2u,
                        a[mt][0], a[mt][1], a[mt][2], a[mt][3]);
            #pragma unroll
            for (int p = 0; p < 4; p++)
                ldsm_x4(Bs + (uint32_t)(b_off + j * 16 + p * 16 * PA) * 2u,
                        bf[2 * p][0], bf[2 * p][1], bf[2 * p + 1][0], bf[2 * p + 1][1]);
            #pragma unroll
            for (int mt = 0; mt < 4; mt++)
                #pragma unroll
                for (int nt = 0; nt < 8; nt++)
                    if (wn * 64 + nt * 8 <= wm * 64 + mt * 16 + 15)   // causal skip
                        mma_f16(acc[mt][nt], a[mt], bf[nt]);
        }
    }

    load_v(0); cp_commit();   // prefetch V stage 0, overlaps softmax

    const float scale = 0.03125f;
    #pragma unroll
    for (int mt = 0; mt < 4; mt++) {
        const int mrow = wm * 64 + mt * 16;
        #pragma unroll
        for (int nt = 0; nt < 8; nt++) {
            const int ncol = wn * 64 + nt * 8 + 2 * tg;
            *reinterpret_cast<__half2*>(P + (mrow + g) * PP + ncol) =
                __float22half2_rn(make_float2(acc[mt][nt][0] * scale, acc[mt][nt][1] * scale));
            *reinterpret_cast<__half2*>(P + (mrow + g + 8) * PP + ncol) =
                __float22half2_rn(make_float2(acc[mt][nt][2] * scale, acc[mt][nt][3] * scale));
        }
    }
    __syncthreads();

    // ---------------- Phase 2: causal softmax (warp per row, 32 rows/warp) --
    #pragma unroll 1
    for (int i = 0; i < 32; i++) {
        const int r = wid * 32 + i;
        float x[4];
        #pragma unroll
        for (int j = 0; j < 4; j++) {
            const int col = lane + 32 * j;
            x[j] = (col <= r) ? __half2float(P[r * PP + col]) : -1e30f;
        }
        float m = fmaxf(fmaxf(x[0], x[1]), fmaxf(x[2], x[3]));
        #pragma unroll
        for (int o = 16; o > 0; o >>= 1) m = fmaxf(m, __shfl_xor_sync(0xffffffffu, m, o));
        float e[4], s = 0.f;
        #pragma unroll
        for (int j = 0; j < 4; j++) {
            const int col = lane + 32 * j;
            e[j] = (col <= r) ? __expf(x[j] - m) : 0.f;
            s += e[j];
        }
        #pragma unroll
        for (int o = 16; o > 0; o >>= 1) s += __shfl_xor_sync(0xffffffffu, s, o);
        const float inv = 1.f / s;
        #pragma unroll
        for (int j = 0; j < 4; j++)
            P[r * PP + lane + 32 * j] = __float2half_rn(e[j] * inv);
    }
    __syncthreads();

    // ---------------- Phase 3: O = P * vT (structural-zero skip) -----------
    // P[m][k]==0 for k>m: chunk ki active for warp tile mt iff mt >= ki - 4*wm
    for (int nt = 0; nt < 8; nt++) {
        #pragma unroll
        for (int i = 0; i < 4; i++)
            #pragma unroll
            for (int j = 0; j < 8; j++)
                #pragma unroll
                for (int c = 0; c < 4; c++) acc[i][j][c] = 0.f;

        for (int ki = 0; ki < 8; ki++) {
            const int s = nt * 8 + ki;
            if (s + 1 < 64) { load_v(s + 1); cp_commit(); cp_wait<1>(); }
            else            { cp_wait<0>(); }
            __syncthreads();
            const uint32_t Vs = smb + (uint32_t)((s & 1) * VST) * 2u;

            const int mt_lo = ki - 4 * wm;
            if (mt_lo <= 3) {
                uint32_t a[4][4], bf[8][2];
                #pragma unroll
                for (int mt = 0; mt < 4; mt++)
                    if (mt >= mt_lo)
                        ldsm_x4(Pu + (uint32_t)(p_off + mt * 16 * PP + ki * 16) * 2u,
                                a[mt][0], a[mt][1], a[mt][2], a[mt][3]);
                #pragma unroll
                for (int p = 0; p < 4; p++)
                    ldsm_x4(Vs + (uint32_t)(bv_off + p * 16 * PV) * 2u,
                            bf[2 * p][0], bf[2 * p][1], bf[2 * p + 1][0], bf[2 * p + 1][1]);
                #pragma unroll
                for (int mt = 0; mt < 4; mt++)
                    if (mt >= mt_lo)
                        #pragma unroll
                        for (int nt2 = 0; nt2 < 8; nt2++)
                            mma_f16(acc[mt][nt2], a[mt], bf[nt2]);
            }
            __syncthreads();
        }

        #pragma unroll
        for (int mt = 0; mt < 4; mt++) {
            const int mrow = wm * 64 + mt * 16;
            #pragma unroll
            for (int nt2 = 0; nt2 < 8; nt2++) {
                const int ncol = nt * 128 + wn * 64 + nt2 * 8 + 2 * tg;
                *reinterpret_cast<float2*>(O + ((size_t)b * SEQ + mrow + g) * HS + ncol) =
                    make_float2(acc[mt][nt2][0], acc[mt][nt2][1]);
                *reinterpret_cast<float2*>(O + ((size_t)b * SEQ + mrow + g + 8) * HS + ncol) =
                    make_float2(acc[mt][nt2][2], acc[mt][nt2][3]);
            }
        }
    }
}

// ===========================================================================
extern "C" void kernel_launch(void* const* d_in, const int* in_sizes, int n_in,
                              void* d_out, int out_size)
{
    const float* query = (const float*)d_in[0];
    const float* key   = (const float*)d_in[1];
    const float* value = (const float*)d_in[2];
    const float* w_q   = (const float*)d_in[3];
    const float* w_k   = (const float*)d_in[4];
    const float* w_v   = (const float*)d_in[5];
    float* out = (float*)d_out;

    prepass<<<dim3(8192, 1, 6), 256>>>(query, key, value, w_q, w_k, w_v);

    cudaFuncSetAttribute(gemm_M, cudaFuncAttributeMaxDynamicSharedMemorySize, GEMM_SMEM);
    gemm_M<<<dim3(8, 8), 128, GEMM_SMEM>>>();

    cudaFuncSetAttribute(proj_f16, cudaFuncAttributeMaxDynamicSharedMemorySize, GEMM_SMEM);
    proj_f16<<<dim3(8, 256, 2), 128, GEMM_SMEM>>>();

    cudaFuncSetAttribute(attn_f16, cudaFuncAttributeMaxDynamicSharedMemorySize, ATTN_SMEM);
    attn_f16<<<BATCH, 128, ATTN_SMEM>>>(out);
}